// round 1
// baseline (speedup 1.0000x reference)
#include <cuda_runtime.h>
#include <math.h>

#define Bsz 4096
#define Ff  1024
#define Ee  16
#define Dd  8
#define Tt  1040
#define Ll  3

// ---------------- scratch (device globals; no allocation allowed) ----------
__device__ __align__(16) float g_xc [Bsz*Tt];
__device__ __align__(16) float g_ch1[Bsz*512];
__device__ __align__(16) float g_ch2[Bsz*256];
__device__ __align__(16) float g_hc [Bsz*128];
__device__ __align__(16) float g_dg1[Bsz*512];
__device__ __align__(16) float g_dg2[Bsz*256];
__device__ __align__(16) float g_hd [Bsz*128];
__device__ float g_aux[Bsz];
__device__ int   g_cnt[Dd];
__device__ int   g_off[Dd];
__device__ int   g_cur[Dd];
__device__ int   g_perm[Bsz];

// ---------------- helpers ---------------------------------------------------
__device__ __forceinline__ float blockReduceSum256(float v, float* red) {
    int tid = threadIdx.x;
    #pragma unroll
    for (int o = 16; o; o >>= 1) v += __shfl_down_sync(0xffffffffu, v, o);
    if ((tid & 31) == 0) red[tid >> 5] = v;
    __syncthreads();
    if (tid < 32) {
        float x = (tid < 8) ? red[tid] : 0.f;
        #pragma unroll
        for (int o = 4; o; o >>= 1) x += __shfl_down_sync(0xffffffffu, x, o);
        if (tid == 0) red[0] = x;
    }
    __syncthreads();
    float r = red[0];
    __syncthreads();
    return r;
}

// ---------------- K0: zero counters ----------------------------------------
__global__ void k_zero() {
    int t = threadIdx.x;
    if (t < Dd) { g_cnt[t] = 0; g_cur[t] = 0; }
}

// ---------------- K1: LayerNorm + domain affine + cross net + aux ----------
__global__ void k_prep(const float* __restrict__ x, const int* __restrict__ dom,
                       const float* __restrict__ pnw, const float* __restrict__ pnb,
                       const float* __restrict__ demb,
                       const float* __restrict__ cw, const float* __restrict__ cb,
                       const float* __restrict__ aW1, const float* __restrict__ ab1,
                       const float* __restrict__ aW2, const float* __restrict__ ab2)
{
    int r = blockIdx.x;
    int tid = threadIdx.x;
    __shared__ float s_x0[Tt];
    __shared__ float s_xc[Tt];
    __shared__ float red[32];

    const float* xr = x + (size_t)r * Ff;
    float sum = 0.f, sq = 0.f;
    for (int j = tid; j < Ff; j += 256) { float v = xr[j]; sum += v; sq += v * v; }
    float tot  = blockReduceSum256(sum, red);
    float tot2 = blockReduceSum256(sq, red);
    float mean = tot * (1.f / Ff);
    float var  = tot2 * (1.f / Ff) - mean * mean;
    float rstd = rsqrtf(var + 1e-5f);

    int d = dom[r];
    const float* wr = pnw + (size_t)d * Ff;
    const float* br = pnb + (size_t)d * Ff;
    for (int j = tid; j < Ff; j += 256) {
        float nv = (xr[j] - mean) * rstd * wr[j] + br[j];
        s_x0[j] = nv;
        s_xc[j] = nv;
    }
    for (int e = tid; e < Ee; e += 256) {
        float v = demb[d * Ee + e];
        s_x0[Ff + e] = v;
        s_xc[Ff + e] = v;
    }
    __syncthreads();

    // cross layers: xc = x0 * (xc . w_i) + b_i + xc
    for (int i = 0; i < Ll; i++) {
        const float* wi = cw + i * Tt;
        const float* bi = cb + i * Tt;
        float p = 0.f;
        for (int j = tid; j < Tt; j += 256) p += s_xc[j] * wi[j];
        float proj = blockReduceSum256(p, red);
        for (int j = tid; j < Tt; j += 256)
            s_xc[j] = fmaf(s_x0[j], proj, bi[j] + s_xc[j]);
        __syncthreads();
    }

    // write xc
    float* out = g_xc + (size_t)r * Tt;
    for (int j = tid; j < Tt; j += 256) out[j] = s_xc[j];

    // aux net on domain embedding (warp 0)
    if (tid < 32) {
        float s = ab1[tid];
        #pragma unroll
        for (int e = 0; e < Ee; e++) s = fmaf(s_x0[Ff + e], aW1[e * 32 + tid], s);
        s = fmaxf(s, 0.f) * aW2[tid];
        #pragma unroll
        for (int o = 16; o; o >>= 1) s += __shfl_down_sync(0xffffffffu, s, o);
        if (tid == 0) g_aux[r] = s + ab2[0];
    }
    if (tid == 0) atomicAdd(&g_cnt[d], 1);
}

// ---------------- K2: prefix offsets ----------------------------------------
__global__ void k_off() {
    if (threadIdx.x == 0) {
        int s = 0;
        for (int d = 0; d < Dd; d++) { g_off[d] = s; s += g_cnt[d]; }
    }
}

// ---------------- K3: fill permutation --------------------------------------
__global__ void k_fill(const int* __restrict__ dom) {
    int r = blockIdx.x * 256 + threadIdx.x;
    if (r < Bsz) {
        int d = dom[r];
        int p = atomicAdd(&g_cur[d], 1);
        g_perm[g_off[d] + p] = r;
    }
}

// ---------------- GEMM: C[M,N] = act(A[M,K] @ W[K,N] + bias) ----------------
// MODE 0: plain, M=Bsz, direct rows.
// MODE 1: domain gather: d=blockIdx.z, A row = perm[slot], C row = slot.
// MODE 2: domain plain:  A row = slot,        C row = slot.
// MODE 3: domain scatter:A row = slot,        C row = perm[slot].
template<int K, int N, bool RELU, int MODE>
__global__ void gemm_k(const float* __restrict__ A, const float* __restrict__ W,
                       const float* __restrict__ bias, float* __restrict__ C)
{
    const int BM = 64, BN = 64, BK = 16;
    __shared__ float As[BK][BM + 1];
    __shared__ float Bs[BK][BN];
    __shared__ int rowA[BM];
    __shared__ int rowC[BM];

    int n0 = blockIdx.x * BN;
    int m0 = blockIdx.y * BM;
    const float* Wp = W;
    const float* bp = bias;
    int cnt = Bsz, off = 0;
    if (MODE > 0) {
        int d = blockIdx.z;
        cnt = g_cnt[d];
        off = g_off[d];
        Wp  = W + (size_t)d * K * N;
        bp  = bias + d * N;
        if (m0 >= cnt) return;
    }

    int tid = threadIdx.x;
    if (tid < BM) {
        int m = m0 + tid;
        if (MODE == 0) { rowA[tid] = m; rowC[tid] = m; }
        else {
            int mm = min(m, cnt - 1);
            int slot = off + mm;
            if (MODE == 1)      { rowA[tid] = g_perm[slot]; rowC[tid] = slot; }
            else if (MODE == 2) { rowA[tid] = slot;         rowC[tid] = slot; }
            else                { rowA[tid] = slot;         rowC[tid] = g_perm[slot]; }
        }
    }
    __syncthreads();

    int ty = tid >> 4, tx = tid & 15;
    int la_m = tid >> 2;          // 0..63
    int la_k = (tid & 3) * 4;     // 0,4,8,12
    int lb_k = tid >> 4;          // 0..15
    int lb_n = (tid & 15) * 4;

    float acc[4][4];
    #pragma unroll
    for (int i = 0; i < 4; i++)
        #pragma unroll
        for (int j = 0; j < 4; j++) acc[i][j] = 0.f;

    for (int k0 = 0; k0 < K; k0 += BK) {
        float4 av = *(const float4*)(A + (size_t)rowA[la_m] * K + k0 + la_k);
        As[la_k + 0][la_m] = av.x;
        As[la_k + 1][la_m] = av.y;
        As[la_k + 2][la_m] = av.z;
        As[la_k + 3][la_m] = av.w;
        float4 bv = *(const float4*)(Wp + (size_t)(k0 + lb_k) * N + n0 + lb_n);
        *(float4*)&Bs[lb_k][lb_n] = bv;
        __syncthreads();
        #pragma unroll
        for (int k = 0; k < BK; k++) {
            float a0 = As[k][ty * 4 + 0];
            float a1 = As[k][ty * 4 + 1];
            float a2 = As[k][ty * 4 + 2];
            float a3 = As[k][ty * 4 + 3];
            float4 b = *(const float4*)&Bs[k][tx * 4];
            acc[0][0] = fmaf(a0, b.x, acc[0][0]); acc[0][1] = fmaf(a0, b.y, acc[0][1]);
            acc[0][2] = fmaf(a0, b.z, acc[0][2]); acc[0][3] = fmaf(a0, b.w, acc[0][3]);
            acc[1][0] = fmaf(a1, b.x, acc[1][0]); acc[1][1] = fmaf(a1, b.y, acc[1][1]);
            acc[1][2] = fmaf(a1, b.z, acc[1][2]); acc[1][3] = fmaf(a1, b.w, acc[1][3]);
            acc[2][0] = fmaf(a2, b.x, acc[2][0]); acc[2][1] = fmaf(a2, b.y, acc[2][1]);
            acc[2][2] = fmaf(a2, b.z, acc[2][2]); acc[2][3] = fmaf(a2, b.w, acc[2][3]);
            acc[3][0] = fmaf(a3, b.x, acc[3][0]); acc[3][1] = fmaf(a3, b.y, acc[3][1]);
            acc[3][2] = fmaf(a3, b.z, acc[3][2]); acc[3][3] = fmaf(a3, b.w, acc[3][3]);
        }
        __syncthreads();
    }

    float4 bb = *(const float4*)&bp[n0 + tx * 4];
    #pragma unroll
    for (int i = 0; i < 4; i++) {
        int m = m0 + ty * 4 + i;
        if (MODE > 0 && m >= cnt) continue;
        float4 v;
        v.x = acc[i][0] + bb.x; v.y = acc[i][1] + bb.y;
        v.z = acc[i][2] + bb.z; v.w = acc[i][3] + bb.w;
        if (RELU) {
            v.x = fmaxf(v.x, 0.f); v.y = fmaxf(v.y, 0.f);
            v.z = fmaxf(v.z, 0.f); v.w = fmaxf(v.w, 0.f);
        }
        *(float4*)&C[(size_t)rowC[ty * 4 + i] * N + n0 + tx * 4] = v;
    }
}

// ---------------- K_final: STAR fusion + final MLP + sigmoid ----------------
__global__ void k_final(const float* __restrict__ fW1, const float* __restrict__ fb1,
                        const float* __restrict__ fW2, const float* __restrict__ fb2,
                        float* __restrict__ out)
{
    int r = blockIdx.x;
    int t = threadIdx.x;
    __shared__ float fs[128];
    __shared__ float red[64];
    fs[t] = g_hc[r * 128 + t] * tanhf(g_hd[r * 128 + t]);
    __syncthreads();
    if (t < 64) {
        float s = fb1[t];
        #pragma unroll
        for (int j = 0; j < 128; j++) s = fmaf(fs[j], fW1[j * 64 + t], s);
        red[t] = fmaxf(s, 0.f) * fW2[t];
    }
    __syncthreads();
    if (t < 32) {
        float v = red[t] + red[t + 32];
        #pragma unroll
        for (int o = 16; o; o >>= 1) v += __shfl_down_sync(0xffffffffu, v, o);
        if (t == 0) {
            float logit = v + fb2[0] + g_aux[r];
            out[r] = 1.f / (1.f + expf(-logit));
        }
    }
}

// ---------------- launch -----------------------------------------------------
extern "C" void kernel_launch(void* const* d_in, const int* in_sizes, int n_in,
                              void* d_out, int out_size)
{
    const float* x    = (const float*)d_in[0];
    const int*   dom  = (const int*)  d_in[1];
    const float* pnw  = (const float*)d_in[2];
    const float* pnb  = (const float*)d_in[3];
    const float* demb = (const float*)d_in[4];
    const float* cw   = (const float*)d_in[5];
    const float* cb   = (const float*)d_in[6];
    const float* cW1  = (const float*)d_in[7];
    const float* cb1  = (const float*)d_in[8];
    const float* cW2  = (const float*)d_in[9];
    const float* cb2  = (const float*)d_in[10];
    const float* cW3  = (const float*)d_in[11];
    const float* cb3  = (const float*)d_in[12];
    const float* dW1  = (const float*)d_in[13];
    const float* db1  = (const float*)d_in[14];
    const float* dW2  = (const float*)d_in[15];
    const float* db2  = (const float*)d_in[16];
    const float* dW3  = (const float*)d_in[17];
    const float* db3  = (const float*)d_in[18];
    const float* fW1  = (const float*)d_in[19];
    const float* fb1  = (const float*)d_in[20];
    const float* fW2  = (const float*)d_in[21];
    const float* fb2  = (const float*)d_in[22];
    const float* aW1  = (const float*)d_in[23];
    const float* ab1  = (const float*)d_in[24];
    const float* aW2  = (const float*)d_in[25];
    const float* ab2  = (const float*)d_in[26];
    float* out = (float*)d_out;

    float *xcP, *ch1P, *ch2P, *hcP, *dg1P, *dg2P, *hdP;
    cudaGetSymbolAddress((void**)&xcP,  g_xc);
    cudaGetSymbolAddress((void**)&ch1P, g_ch1);
    cudaGetSymbolAddress((void**)&ch2P, g_ch2);
    cudaGetSymbolAddress((void**)&hcP,  g_hc);
    cudaGetSymbolAddress((void**)&dg1P, g_dg1);
    cudaGetSymbolAddress((void**)&dg2P, g_dg2);
    cudaGetSymbolAddress((void**)&hdP,  g_hd);

    k_zero<<<1, 32>>>();
    k_prep<<<Bsz, 256>>>(x, dom, pnw, pnb, demb, cw, cb, aW1, ab1, aW2, ab2);
    k_off<<<1, 32>>>();
    k_fill<<<Bsz / 256, 256>>>(dom);

    // center MLP
    gemm_k<Tt,  512, true,  0><<<dim3(8, 64, 1), 256>>>(xcP,  cW1, cb1, ch1P);
    gemm_k<512, 256, true,  0><<<dim3(4, 64, 1), 256>>>(ch1P, cW2, cb2, ch2P);
    gemm_k<256, 128, false, 0><<<dim3(2, 64, 1), 256>>>(ch2P, cW3, cb3, hcP);

    // domain nets (grouped by domain; only selected net per sample)
    gemm_k<Tt,  512, true,  1><<<dim3(8, 64, Dd), 256>>>(xcP,  dW1, db1, dg1P);
    gemm_k<512, 256, true,  2><<<dim3(4, 64, Dd), 256>>>(dg1P, dW2, db2, dg2P);
    gemm_k<256, 128, false, 3><<<dim3(2, 64, Dd), 256>>>(dg2P, dW3, db3, hdP);

    k_final<<<Bsz, 128>>>(fW1, fb1, fW2, fb2, out);
}

// round 2
// speedup vs baseline: 2.2472x; 2.2472x over previous
#include <cuda_runtime.h>
#include <math.h>

#define Bsz 4096
#define Ff  1024
#define Ee  16
#define Dd  8
#define Tt  1040
#define Ll  3

// ---------------- scratch (device globals; no allocation allowed) ----------
__device__ __align__(16) float g_xc [Bsz*Tt];
__device__ __align__(16) float g_ch1[Bsz*512];
__device__ __align__(16) float g_ch2[Bsz*256];
__device__ __align__(16) float g_hc [Bsz*128];
__device__ __align__(16) float g_dg1[Bsz*512];
__device__ __align__(16) float g_dg2[Bsz*256];
__device__ __align__(16) float g_hd [Bsz*128];
__device__ float g_aux[Bsz];
__device__ int   g_cnt[Dd];
__device__ int   g_off[Dd];
__device__ int   g_cur[Dd];
__device__ int   g_perm[Bsz];

// ---------------- helpers ---------------------------------------------------
__device__ __forceinline__ float blockReduceSum256(float v, float* red) {
    int tid = threadIdx.x;
    #pragma unroll
    for (int o = 16; o; o >>= 1) v += __shfl_down_sync(0xffffffffu, v, o);
    if ((tid & 31) == 0) red[tid >> 5] = v;
    __syncthreads();
    if (tid < 32) {
        float x = (tid < 8) ? red[tid] : 0.f;
        #pragma unroll
        for (int o = 4; o; o >>= 1) x += __shfl_down_sync(0xffffffffu, x, o);
        if (tid == 0) red[0] = x;
    }
    __syncthreads();
    float r = red[0];
    __syncthreads();
    return r;
}

__device__ __forceinline__ unsigned f2tf(float x) {
    unsigned u;
    asm("cvt.rna.tf32.f32 %0, %1;" : "=r"(u) : "f"(x));
    return u;
}

__device__ __forceinline__ void mma_tf32(float* c, const unsigned* a, const unsigned* b) {
    asm("mma.sync.aligned.m16n8k8.row.col.f32.tf32.tf32.f32 "
        "{%0,%1,%2,%3}, {%4,%5,%6,%7}, {%8,%9}, {%0,%1,%2,%3};\n"
        : "+f"(c[0]), "+f"(c[1]), "+f"(c[2]), "+f"(c[3])
        : "r"(a[0]), "r"(a[1]), "r"(a[2]), "r"(a[3]), "r"(b[0]), "r"(b[1]));
}

// ---------------- K0: zero counters ----------------------------------------
__global__ void k_zero() {
    int t = threadIdx.x;
    if (t < Dd) { g_cnt[t] = 0; g_cur[t] = 0; }
}

// ---------------- K1: LayerNorm + domain affine + cross net + aux ----------
__global__ void k_prep(const float* __restrict__ x, const int* __restrict__ dom,
                       const float* __restrict__ pnw, const float* __restrict__ pnb,
                       const float* __restrict__ demb,
                       const float* __restrict__ cw, const float* __restrict__ cb,
                       const float* __restrict__ aW1, const float* __restrict__ ab1,
                       const float* __restrict__ aW2, const float* __restrict__ ab2)
{
    int r = blockIdx.x;
    int tid = threadIdx.x;
    __shared__ float s_x0[Tt];
    __shared__ float s_xc[Tt];
    __shared__ float red[32];

    const float* xr = x + (size_t)r * Ff;
    float sum = 0.f, sq = 0.f;
    for (int j = tid; j < Ff; j += 256) { float v = xr[j]; sum += v; sq += v * v; }
    float tot  = blockReduceSum256(sum, red);
    float tot2 = blockReduceSum256(sq, red);
    float mean = tot * (1.f / Ff);
    float var  = tot2 * (1.f / Ff) - mean * mean;
    float rstd = rsqrtf(var + 1e-5f);

    int d = dom[r];
    const float* wr = pnw + (size_t)d * Ff;
    const float* br = pnb + (size_t)d * Ff;
    for (int j = tid; j < Ff; j += 256) {
        float nv = (xr[j] - mean) * rstd * wr[j] + br[j];
        s_x0[j] = nv;
        s_xc[j] = nv;
    }
    for (int e = tid; e < Ee; e += 256) {
        float v = demb[d * Ee + e];
        s_x0[Ff + e] = v;
        s_xc[Ff + e] = v;
    }
    __syncthreads();

    // cross layers: xc = x0 * (xc . w_i) + b_i + xc
    for (int i = 0; i < Ll; i++) {
        const float* wi = cw + i * Tt;
        const float* bi = cb + i * Tt;
        float p = 0.f;
        for (int j = tid; j < Tt; j += 256) p += s_xc[j] * wi[j];
        float proj = blockReduceSum256(p, red);
        for (int j = tid; j < Tt; j += 256)
            s_xc[j] = fmaf(s_x0[j], proj, bi[j] + s_xc[j]);
        __syncthreads();
    }

    // write xc
    float* out = g_xc + (size_t)r * Tt;
    for (int j = tid; j < Tt; j += 256) out[j] = s_xc[j];

    // aux net on domain embedding (warp 0)
    if (tid < 32) {
        float s = ab1[tid];
        #pragma unroll
        for (int e = 0; e < Ee; e++) s = fmaf(s_x0[Ff + e], aW1[e * 32 + tid], s);
        s = fmaxf(s, 0.f) * aW2[tid];
        #pragma unroll
        for (int o = 16; o; o >>= 1) s += __shfl_down_sync(0xffffffffu, s, o);
        if (tid == 0) g_aux[r] = s + ab2[0];
    }
    if (tid == 0) atomicAdd(&g_cnt[d], 1);
}

// ---------------- K2: prefix offsets ----------------------------------------
__global__ void k_off() {
    if (threadIdx.x == 0) {
        int s = 0;
        for (int d = 0; d < Dd; d++) { g_off[d] = s; s += g_cnt[d]; }
    }
}

// ---------------- K3: fill permutation --------------------------------------
__global__ void k_fill(const int* __restrict__ dom) {
    int r = blockIdx.x * 256 + threadIdx.x;
    if (r < Bsz) {
        int d = dom[r];
        int p = atomicAdd(&g_cur[d], 1);
        g_perm[g_off[d] + p] = r;
    }
}

// ---------------- TF32 tensor-core GEMM -------------------------------------
// One launch handles the center net (z==0) and all 8 domain nets (z=1..8).
// C[M,N] = act(A[M,K] @ W[K,N] + bias)
// LAYER 1: domain A rows gathered via perm, C rows = packed slots
// LAYER 2: domain A/C rows = packed slots
// LAYER 3: domain A rows = packed slots, C rows scattered via perm
#define BM 128
#define BN 128
#define LDA 136
#define LDB 136

template<int K, int N, bool RELU, int LAYER>
__global__ __launch_bounds__(256)
void gemm_tc(const float* __restrict__ Ac, const float* __restrict__ Ad,
             const float* __restrict__ Wc, const float* __restrict__ Wd,
             const float* __restrict__ bc, const float* __restrict__ bd,
             float* __restrict__ Cc, float* __restrict__ Cd)
{
    __shared__ unsigned As[2][16][LDA];
    __shared__ unsigned Bs[2][16][LDB];
    __shared__ int rowA[BM], rowC[BM];

    const int z  = blockIdx.z;
    const int n0 = blockIdx.x * BN;
    const int m0 = blockIdx.y * BM;

    const float *A, *W, *bias;
    float* C;
    int cnt;
    if (z == 0) {
        A = Ac; W = Wc; bias = bc; C = Cc; cnt = Bsz;
    } else {
        int d = z - 1;
        cnt = g_cnt[d];
        if (m0 >= cnt) return;
        A = Ad; W = Wd + (size_t)d * K * N; bias = bd + d * N; C = Cd;
    }

    const int tid = threadIdx.x;
    if (tid < BM) {
        if (z == 0) { rowA[tid] = m0 + tid; rowC[tid] = m0 + tid; }
        else {
            int off  = g_off[z - 1];
            int mm   = min(m0 + tid, cnt - 1);
            int slot = off + mm;
            if (LAYER == 1)      { rowA[tid] = g_perm[slot]; rowC[tid] = slot; }
            else if (LAYER == 2) { rowA[tid] = slot;         rowC[tid] = slot; }
            else                 { rowA[tid] = slot;         rowC[tid] = g_perm[slot]; }
        }
    }
    __syncthreads();

    // loader mapping
    const int la_m = tid & 127;          // m row this thread loads
    const int la_h = (tid >> 7) * 8;     // k offset 0 or 8
    const int lb_n = (tid & 31) * 4;     // n col (float4)
    const int lb_k = tid >> 5;           // k row 0..7 (and +8)
    const float* aRowPtr = A + (size_t)rowA[la_m] * K;

    // warp/fragment mapping
    const int wid  = tid >> 5;
    const int lane = tid & 31;
    const int gid  = lane >> 2;
    const int tig  = lane & 3;
    const int wm   = (wid & 1) * 64;     // warp tile 64 (m) x 32 (n)
    const int wn   = (wid >> 1) * 32;

    float acc[4][4][4];
    #pragma unroll
    for (int mt = 0; mt < 4; mt++)
        #pragma unroll
        for (int nt = 0; nt < 4; nt++)
            #pragma unroll
            for (int i = 0; i < 4; i++) acc[mt][nt][i] = 0.f;

    float a_reg[8];
    float b_reg[8];

    // prologue: load tile 0
    {
        const float* ap = aRowPtr + la_h;
        float4 v0 = *(const float4*)ap;
        float4 v1 = *(const float4*)(ap + 4);
        a_reg[0] = v0.x; a_reg[1] = v0.y; a_reg[2] = v0.z; a_reg[3] = v0.w;
        a_reg[4] = v1.x; a_reg[5] = v1.y; a_reg[6] = v1.z; a_reg[7] = v1.w;
        float4 w0 = *(const float4*)(W + (size_t)lb_k * N + n0 + lb_n);
        float4 w1 = *(const float4*)(W + (size_t)(lb_k + 8) * N + n0 + lb_n);
        b_reg[0] = w0.x; b_reg[1] = w0.y; b_reg[2] = w0.z; b_reg[3] = w0.w;
        b_reg[4] = w1.x; b_reg[5] = w1.y; b_reg[6] = w1.z; b_reg[7] = w1.w;
        #pragma unroll
        for (int i = 0; i < 8; i++) As[0][la_h + i][la_m] = f2tf(a_reg[i]);
        uint4 s0 = { f2tf(b_reg[0]), f2tf(b_reg[1]), f2tf(b_reg[2]), f2tf(b_reg[3]) };
        uint4 s1 = { f2tf(b_reg[4]), f2tf(b_reg[5]), f2tf(b_reg[6]), f2tf(b_reg[7]) };
        *(uint4*)&Bs[0][lb_k][lb_n]     = s0;
        *(uint4*)&Bs[0][lb_k + 8][lb_n] = s1;
    }
    __syncthreads();

    const int ITERS = K / 16;
    for (int it = 0; it < ITERS; ++it) {
        const int buf = it & 1;

        // prefetch next k-tile into registers
        if (it + 1 < ITERS) {
            const int k0 = (it + 1) * 16;
            const float* ap = aRowPtr + k0 + la_h;
            float4 v0 = *(const float4*)ap;
            float4 v1 = *(const float4*)(ap + 4);
            a_reg[0] = v0.x; a_reg[1] = v0.y; a_reg[2] = v0.z; a_reg[3] = v0.w;
            a_reg[4] = v1.x; a_reg[5] = v1.y; a_reg[6] = v1.z; a_reg[7] = v1.w;
            float4 w0 = *(const float4*)(W + (size_t)(k0 + lb_k) * N + n0 + lb_n);
            float4 w1 = *(const float4*)(W + (size_t)(k0 + lb_k + 8) * N + n0 + lb_n);
            b_reg[0] = w0.x; b_reg[1] = w0.y; b_reg[2] = w0.z; b_reg[3] = w0.w;
            b_reg[4] = w1.x; b_reg[5] = w1.y; b_reg[6] = w1.z; b_reg[7] = w1.w;
        }

        // compute on current buffer
        #pragma unroll
        for (int kk = 0; kk < 16; kk += 8) {
            unsigned af[4][4], bf[4][2];
            #pragma unroll
            for (int mt = 0; mt < 4; mt++) {
                int m = wm + mt * 16 + gid;
                af[mt][0] = As[buf][kk + tig][m];
                af[mt][1] = As[buf][kk + tig][m + 8];
                af[mt][2] = As[buf][kk + tig + 4][m];
                af[mt][3] = As[buf][kk + tig + 4][m + 8];
            }
            #pragma unroll
            for (int nt = 0; nt < 4; nt++) {
                int n = wn + nt * 8 + gid;
                bf[nt][0] = Bs[buf][kk + tig][n];
                bf[nt][1] = Bs[buf][kk + tig + 4][n];
            }
            #pragma unroll
            for (int mt = 0; mt < 4; mt++)
                #pragma unroll
                for (int nt = 0; nt < 4; nt++)
                    mma_tf32(acc[mt][nt], af[mt], bf[nt]);
        }

        // store prefetched tile into the other buffer
        if (it + 1 < ITERS) {
            const int nb = buf ^ 1;
            #pragma unroll
            for (int i = 0; i < 8; i++) As[nb][la_h + i][la_m] = f2tf(a_reg[i]);
            uint4 s0 = { f2tf(b_reg[0]), f2tf(b_reg[1]), f2tf(b_reg[2]), f2tf(b_reg[3]) };
            uint4 s1 = { f2tf(b_reg[4]), f2tf(b_reg[5]), f2tf(b_reg[6]), f2tf(b_reg[7]) };
            *(uint4*)&Bs[nb][lb_k][lb_n]     = s0;
            *(uint4*)&Bs[nb][lb_k + 8][lb_n] = s1;
        }
        __syncthreads();
    }

    // epilogue: bias + activation + store
    #pragma unroll
    for (int mt = 0; mt < 4; mt++) {
        int mr0 = wm + mt * 16 + gid;
        int mr1 = mr0 + 8;
        bool v0 = (z == 0) || (m0 + mr0 < cnt);
        bool v1 = (z == 0) || (m0 + mr1 < cnt);
        #pragma unroll
        for (int nt = 0; nt < 4; nt++) {
            int col = n0 + wn + nt * 8 + 2 * tig;
            float bx = bias[col], by = bias[col + 1];
            float2 r0, r1;
            r0.x = acc[mt][nt][0] + bx; r0.y = acc[mt][nt][1] + by;
            r1.x = acc[mt][nt][2] + bx; r1.y = acc[mt][nt][3] + by;
            if (RELU) {
                r0.x = fmaxf(r0.x, 0.f); r0.y = fmaxf(r0.y, 0.f);
                r1.x = fmaxf(r1.x, 0.f); r1.y = fmaxf(r1.y, 0.f);
            }
            if (v0) *(float2*)&C[(size_t)rowC[mr0] * N + col] = r0;
            if (v1) *(float2*)&C[(size_t)rowC[mr1] * N + col] = r1;
        }
    }
}

// ---------------- K_final: STAR fusion + final MLP + sigmoid ----------------
__global__ void k_final(const float* __restrict__ fW1, const float* __restrict__ fb1,
                        const float* __restrict__ fW2, const float* __restrict__ fb2,
                        float* __restrict__ out)
{
    int r = blockIdx.x;
    int t = threadIdx.x;
    __shared__ float fs[128];
    __shared__ float red[64];
    fs[t] = g_hc[r * 128 + t] * tanhf(g_hd[r * 128 + t]);
    __syncthreads();
    if (t < 64) {
        float s = fb1[t];
        #pragma unroll
        for (int j = 0; j < 128; j++) s = fmaf(fs[j], fW1[j * 64 + t], s);
        red[t] = fmaxf(s, 0.f) * fW2[t];
    }
    __syncthreads();
    if (t < 32) {
        float v = red[t] + red[t + 32];
        #pragma unroll
        for (int o = 16; o; o >>= 1) v += __shfl_down_sync(0xffffffffu, v, o);
        if (t == 0) {
            float logit = v + fb2[0] + g_aux[r];
            out[r] = 1.f / (1.f + expf(-logit));
        }
    }
}

// ---------------- launch -----------------------------------------------------
extern "C" void kernel_launch(void* const* d_in, const int* in_sizes, int n_in,
                              void* d_out, int out_size)
{
    const float* x    = (const float*)d_in[0];
    const int*   dom  = (const int*)  d_in[1];
    const float* pnw  = (const float*)d_in[2];
    const float* pnb  = (const float*)d_in[3];
    const float* demb = (const float*)d_in[4];
    const float* cw   = (const float*)d_in[5];
    const float* cb   = (const float*)d_in[6];
    const float* cW1  = (const float*)d_in[7];
    const float* cb1  = (const float*)d_in[8];
    const float* cW2  = (const float*)d_in[9];
    const float* cb2  = (const float*)d_in[10];
    const float* cW3  = (const float*)d_in[11];
    const float* cb3  = (const float*)d_in[12];
    const float* dW1  = (const float*)d_in[13];
    const float* db1  = (const float*)d_in[14];
    const float* dW2  = (const float*)d_in[15];
    const float* db2  = (const float*)d_in[16];
    const float* dW3  = (const float*)d_in[17];
    const float* db3  = (const float*)d_in[18];
    const float* fW1  = (const float*)d_in[19];
    const float* fb1  = (const float*)d_in[20];
    const float* fW2  = (const float*)d_in[21];
    const float* fb2  = (const float*)d_in[22];
    const float* aW1  = (const float*)d_in[23];
    const float* ab1  = (const float*)d_in[24];
    const float* aW2  = (const float*)d_in[25];
    const float* ab2  = (const float*)d_in[26];
    float* out = (float*)d_out;

    float *xcP, *ch1P, *ch2P, *hcP, *dg1P, *dg2P, *hdP;
    cudaGetSymbolAddress((void**)&xcP,  g_xc);
    cudaGetSymbolAddress((void**)&ch1P, g_ch1);
    cudaGetSymbolAddress((void**)&ch2P, g_ch2);
    cudaGetSymbolAddress((void**)&hcP,  g_hc);
    cudaGetSymbolAddress((void**)&dg1P, g_dg1);
    cudaGetSymbolAddress((void**)&dg2P, g_dg2);
    cudaGetSymbolAddress((void**)&hdP,  g_hd);

    k_zero<<<1, 32>>>();
    k_prep<<<Bsz, 256>>>(x, dom, pnw, pnb, demb, cw, cb, aW1, ab1, aW2, ab2);
    k_off<<<1, 32>>>();
    k_fill<<<Bsz / 256, 256>>>(dom);

    // layer 1: center (z=0) + 8 domain nets (z=1..8), K=1040 -> N=512
    gemm_tc<Tt,  512, true,  1><<<dim3(4, 32, 9), 256>>>(xcP,  xcP,  cW1, dW1, cb1, db1, ch1P, dg1P);
    // layer 2: K=512 -> N=256
    gemm_tc<512, 256, true,  2><<<dim3(2, 32, 9), 256>>>(ch1P, dg1P, cW2, dW2, cb2, db2, ch2P, dg2P);
    // layer 3: K=256 -> N=128
    gemm_tc<256, 128, false, 3><<<dim3(1, 32, 9), 256>>>(ch2P, dg2P, cW3, dW3, cb3, db3, hcP, hdP);

    k_final<<<Bsz, 128>>>(fW1, fb1, fW2, fb2, out);
}

// round 4
// speedup vs baseline: 4.0923x; 1.8211x over previous
#include <cuda_runtime.h>
#include <cuda_fp16.h>
#include <cstdint>
#include <math.h>

#define Bsz 4096
#define Ff  1024
#define Ee  16
#define Dd  8
#define Tt  1040
#define Ll  3
#define K1P 1056   // padded K for layer 1 (multiple of 32)

// ---------------- scratch (device globals; no allocation allowed) ----------
__device__ __align__(128) __half g_xc [Bsz*K1P];
__device__ __align__(128) __half g_ch1[Bsz*512];
__device__ __align__(128) __half g_ch2[Bsz*256];
__device__ __align__(128) __half g_hc [Bsz*128];
__device__ __align__(128) __half g_dg1[Bsz*512];
__device__ __align__(128) __half g_dg2[Bsz*256];
__device__ __align__(128) __half g_hd [Bsz*128];
// transposed, K-padded, half weights: WT[n][k]
__device__ __align__(128) __half g_wt1c[512*K1P];
__device__ __align__(128) __half g_wt1d[Dd*512*K1P];
__device__ __align__(128) __half g_wt2c[256*512];
__device__ __align__(128) __half g_wt2d[Dd*256*512];
__device__ __align__(128) __half g_wt3c[128*256];
__device__ __align__(128) __half g_wt3d[Dd*128*256];
__device__ float g_aux[Bsz];
__device__ int   g_cnt[Dd];
__device__ int   g_off[Dd];
__device__ int   g_perm[Bsz];

// ---------------- PTX helpers ----------------------------------------------
__device__ __forceinline__ uint32_t smem_u32(const void* p) {
    uint32_t a;
    asm("{ .reg .u64 t; cvta.to.shared.u64 t, %1; cvt.u32.u64 %0, t; }" : "=r"(a) : "l"(p));
    return a;
}
__device__ __forceinline__ void ldsm4(uint32_t* r, uint32_t addr) {
    asm volatile("ldmatrix.sync.aligned.m8n8.x4.shared.b16 {%0,%1,%2,%3}, [%4];"
        : "=r"(r[0]), "=r"(r[1]), "=r"(r[2]), "=r"(r[3]) : "r"(addr));
}
__device__ __forceinline__ void mma_f16(float* c, const uint32_t* a, const uint32_t* b) {
    asm volatile("mma.sync.aligned.m16n8k16.row.col.f32.f16.f16.f32 "
        "{%0,%1,%2,%3}, {%4,%5,%6,%7}, {%8,%9}, {%0,%1,%2,%3};"
        : "+f"(c[0]), "+f"(c[1]), "+f"(c[2]), "+f"(c[3])
        : "r"(a[0]), "r"(a[1]), "r"(a[2]), "r"(a[3]), "r"(b[0]), "r"(b[1]));
}

// ---------------- block reduce ----------------------------------------------
__device__ __forceinline__ float blockReduceSum256(float v, float* red) {
    int tid = threadIdx.x;
    #pragma unroll
    for (int o = 16; o; o >>= 1) v += __shfl_down_sync(0xffffffffu, v, o);
    if ((tid & 31) == 0) red[tid >> 5] = v;
    __syncthreads();
    if (tid < 32) {
        float x = (tid < 8) ? red[tid] : 0.f;
        #pragma unroll
        for (int o = 4; o; o >>= 1) x += __shfl_down_sync(0xffffffffu, x, o);
        if (tid == 0) red[0] = x;
    }
    __syncthreads();
    float r = red[0];
    __syncthreads();
    return r;
}

// ---------------- weight transpose + fp32->half (with K padding) ------------
template<int KIN, int NN, int KPAD>
__global__ void k_transpose(const float* __restrict__ in, __half* __restrict__ out) {
    __shared__ float t[32][33];
    int d  = blockIdx.z;
    int nb = blockIdx.x * 32, kb = blockIdx.y * 32;
    const float* ip = in + (size_t)d * KIN * NN;
    __half* op = out + (size_t)d * NN * KPAD;
    int tx = threadIdx.x, ty = threadIdx.y;  // 32 x 8
    #pragma unroll
    for (int i = 0; i < 32; i += 8) {
        int k = kb + ty + i, n = nb + tx;
        t[ty + i][tx] = (k < KIN) ? ip[(size_t)k * NN + n] : 0.f;
    }
    __syncthreads();
    #pragma unroll
    for (int i = 0; i < 32; i += 8) {
        int n = nb + ty + i, k = kb + tx;
        op[(size_t)n * KPAD + k] = __float2half_rn(t[tx][ty + i]);
    }
}

// ---------------- partition: counts, offsets, permutation (one block) -------
__global__ void k_part(const int* __restrict__ dom) {
    __shared__ int scnt[Dd], soff[Dd], scur[Dd];
    int t = threadIdx.x;
    if (t < Dd) { scnt[t] = 0; scur[t] = 0; }
    __syncthreads();
    int dv[4];
    #pragma unroll
    for (int i = 0; i < 4; i++) { dv[i] = dom[t + 1024 * i]; atomicAdd(&scnt[dv[i]], 1); }
    __syncthreads();
    if (t == 0) {
        int s = 0;
        for (int d = 0; d < Dd; d++) { soff[d] = s; g_off[d] = s; g_cnt[d] = scnt[d]; s += scnt[d]; }
    }
    __syncthreads();
    #pragma unroll
    for (int i = 0; i < 4; i++) {
        int p = atomicAdd(&scur[dv[i]], 1);
        g_perm[soff[dv[i]] + p] = t + 1024 * i;
    }
}

// ---------------- K1: LayerNorm + domain affine + cross net + aux ----------
__global__ void k_prep(const float* __restrict__ x, const int* __restrict__ dom,
                       const float* __restrict__ pnw, const float* __restrict__ pnb,
                       const float* __restrict__ demb,
                       const float* __restrict__ cw, const float* __restrict__ cb,
                       const float* __restrict__ aW1, const float* __restrict__ ab1,
                       const float* __restrict__ aW2, const float* __restrict__ ab2)
{
    int r = blockIdx.x;
    int tid = threadIdx.x;
    __shared__ float s_x0[Tt];
    __shared__ float s_xc[Tt];
    __shared__ float red[32];

    const float* xr = x + (size_t)r * Ff;
    float sum = 0.f, sq = 0.f;
    for (int j = tid; j < Ff; j += 256) { float v = xr[j]; sum += v; sq += v * v; }
    float tot  = blockReduceSum256(sum, red);
    float tot2 = blockReduceSum256(sq, red);
    float mean = tot * (1.f / Ff);
    float var  = tot2 * (1.f / Ff) - mean * mean;
    float rstd = rsqrtf(var + 1e-5f);

    int d = dom[r];
    const float* wr = pnw + (size_t)d * Ff;
    const float* br = pnb + (size_t)d * Ff;
    for (int j = tid; j < Ff; j += 256) {
        float nv = (xr[j] - mean) * rstd * wr[j] + br[j];
        s_x0[j] = nv;
        s_xc[j] = nv;
    }
    for (int e = tid; e < Ee; e += 256) {
        float v = demb[d * Ee + e];
        s_x0[Ff + e] = v;
        s_xc[Ff + e] = v;
    }
    __syncthreads();

    for (int i = 0; i < Ll; i++) {
        const float* wi = cw + i * Tt;
        const float* bi = cb + i * Tt;
        float p = 0.f;
        for (int j = tid; j < Tt; j += 256) p += s_xc[j] * wi[j];
        float proj = blockReduceSum256(p, red);
        for (int j = tid; j < Tt; j += 256)
            s_xc[j] = fmaf(s_x0[j], proj, bi[j] + s_xc[j]);
        __syncthreads();
    }

    __half* out = g_xc + (size_t)r * K1P;
    for (int j = tid; j < Tt; j += 256) out[j] = __float2half_rn(s_xc[j]);
    if (tid < K1P - Tt) out[Tt + tid] = __float2half_rn(0.f);

    if (tid < 32) {
        float s = ab1[tid];
        #pragma unroll
        for (int e = 0; e < Ee; e++) s = fmaf(s_x0[Ff + e], aW1[e * 32 + tid], s);
        s = fmaxf(s, 0.f) * aW2[tid];
        #pragma unroll
        for (int o = 16; o; o >>= 1) s += __shfl_down_sync(0xffffffffu, s, o);
        if (tid == 0) g_aux[r] = s + ab2[0];
    }
}

// ---------------- fp16 tensor-core GEMM --------------------------------------
// C[M,N](half) = act(A[M,K](half) @ WT[N,K](half)^T + bias(fp32))
// z=0: center, z=1..8: domain nets. 128x128 tile, BK=32, double-buffered smem,
// ldmatrix fragment loads, m16n8k16 HMMA, smem-staged coalesced epilogue.
#define BK   32
#define LDH  40            // halfs per smem tile row (pad for conflict-free)
#define TSZ  (128*LDH)     // halfs per tile buffer

template<int K, int N, bool RELU, int LAYER>
__global__ __launch_bounds__(256)
void gemm_f16(const __half* __restrict__ Ac, const __half* __restrict__ Ad,
              const __half* __restrict__ Wc, const __half* __restrict__ Wd,
              const float* __restrict__ bc, const float* __restrict__ bd,
              __half* __restrict__ Cc, __half* __restrict__ Cd)
{
    __shared__ __align__(16) __half tiles[4 * TSZ]; // As0 As1 Bs0 Bs1 (40KB)
    __shared__ int rowA[128], rowC[128];

    const int z  = blockIdx.z;
    const int n0 = blockIdx.x * 128;
    const int m0 = blockIdx.y * 128;

    const __half *A, *WT;
    const float* bias;
    __half* C;
    int cnt;
    if (z == 0) { A = Ac; WT = Wc; bias = bc; C = Cc; cnt = Bsz; }
    else {
        int d = z - 1;
        cnt = g_cnt[d];
        if (m0 >= cnt) return;
        A = Ad; WT = Wd + (size_t)d * N * K; bias = bd + d * N; C = Cd;
    }

    const int tid  = threadIdx.x;
    const int wid  = tid >> 5;
    const int lane = tid & 31;

    if (tid < 128) {
        if (z == 0) { rowA[tid] = m0 + tid; rowC[tid] = m0 + tid; }
        else {
            int off = g_off[z - 1];
            int mm  = min(m0 + tid, cnt - 1);
            int slot = off + mm;
            if (LAYER == 1)      { rowA[tid] = g_perm[slot]; rowC[tid] = slot; }
            else if (LAYER == 2) { rowA[tid] = slot;         rowC[tid] = slot; }
            else                 { rowA[tid] = slot;         rowC[tid] = g_perm[slot]; }
        }
    }
    __syncthreads();

    // loader mapping: 2 slots/thread, each 8 halfs (16B)
    const __half* aSrc[2];
    const __half* bSrc[2];
    int dstOff[2];
    #pragma unroll
    for (int i = 0; i < 2; i++) {
        int slot = tid + 256 * i;           // 0..511
        int r  = slot >> 2;                  // 0..127
        int c8 = (slot & 3) * 8;             // 0,8,16,24
        aSrc[i] = A  + (size_t)rowA[r] * K + c8;
        bSrc[i] = WT + (size_t)(n0 + r) * K + c8;
        dstOff[i] = r * LDH + c8;
    }

    const uint32_t sbase = smem_u32(tiles);

    // fragment ldmatrix address components
    const int wm = (wid & 1) * 64;
    const int wn = (wid >> 1) * 32;
    const int gid = lane >> 2, tig = lane & 3;
    const uint32_t aRowOff = (uint32_t)((wm + (lane & 15)) * LDH + ((lane >> 4) * 8)) * 2;
    const uint32_t bRowOff = (uint32_t)((wn + ((lane >> 4) * 8) + (lane & 7)) * LDH
                                        + (((lane >> 3) & 1) * 8)) * 2;

    float acc[4][4][4];
    #pragma unroll
    for (int mt = 0; mt < 4; mt++)
        #pragma unroll
        for (int nt = 0; nt < 4; nt++)
            #pragma unroll
            for (int i = 0; i < 4; i++) acc[mt][nt][i] = 0.f;

    uint4 pa[2], pb[2];

    // prologue: chunk 0 -> buffer 0
    #pragma unroll
    for (int i = 0; i < 2; i++) {
        pa[i] = *(const uint4*)(aSrc[i]);
        pb[i] = *(const uint4*)(bSrc[i]);
        *(uint4*)(tiles + 0 * TSZ + dstOff[i]) = pa[i];
        *(uint4*)(tiles + 2 * TSZ + dstOff[i]) = pb[i];
    }
    __syncthreads();

    const int NCH = K / BK;
    for (int c = 0; c < NCH; c++) {
        const int buf = c & 1;

        if (c + 1 < NCH) {
            int k0 = (c + 1) * BK;
            #pragma unroll
            for (int i = 0; i < 2; i++) {
                pa[i] = *(const uint4*)(aSrc[i] + k0);
                pb[i] = *(const uint4*)(bSrc[i] + k0);
            }
        }

        const uint32_t aB = sbase + buf * (TSZ * 2);
        const uint32_t bB = sbase + (2 + buf) * (TSZ * 2);
        #pragma unroll
        for (int kk = 0; kk < BK; kk += 16) {
            uint32_t af[4][4];
            #pragma unroll
            for (int mt = 0; mt < 4; mt++)
                ldsm4(af[mt], aB + aRowOff + (uint32_t)(mt * 16 * LDH + kk) * 2);
            #pragma unroll
            for (int ntp = 0; ntp < 2; ntp++) {
                uint32_t bf[4];
                ldsm4(bf, bB + bRowOff + (uint32_t)(ntp * 16 * LDH + kk) * 2);
                #pragma unroll
                for (int mt = 0; mt < 4; mt++) {
                    mma_f16(acc[mt][ntp * 2 + 0], af[mt], bf + 0);
                    mma_f16(acc[mt][ntp * 2 + 1], af[mt], bf + 2);
                }
            }
        }

        if (c + 1 < NCH) {
            const int nb = buf ^ 1;
            #pragma unroll
            for (int i = 0; i < 2; i++) {
                *(uint4*)(tiles + nb * TSZ + dstOff[i])       = pa[i];
                *(uint4*)(tiles + (2 + nb) * TSZ + dstOff[i]) = pb[i];
            }
        }
        __syncthreads();
    }

    // epilogue: bias + act -> half, stage in smem, coalesced store
    __half* stage = tiles;      // 128 x 136 halfs = 34816 B < 40960 B
    #pragma unroll
    for (int mt = 0; mt < 4; mt++) {
        #pragma unroll
        for (int nt = 0; nt < 4; nt++) {
            int col = wn + nt * 8 + 2 * tig;
            float bx = bias[n0 + col], by = bias[n0 + col + 1];
            float v0 = acc[mt][nt][0] + bx, v1 = acc[mt][nt][1] + by;
            float v2 = acc[mt][nt][2] + bx, v3 = acc[mt][nt][3] + by;
            if (RELU) {
                v0 = fmaxf(v0, 0.f); v1 = fmaxf(v1, 0.f);
                v2 = fmaxf(v2, 0.f); v3 = fmaxf(v3, 0.f);
            }
            int r0 = wm + mt * 16 + gid;
            *(__half2*)&stage[r0 * 136 + col]       = __floats2half2_rn(v0, v1);
            *(__half2*)&stage[(r0 + 8) * 136 + col] = __floats2half2_rn(v2, v3);
        }
    }
    __syncthreads();
    #pragma unroll
    for (int i = 0; i < 8; i++) {
        int idx = tid + 256 * i;            // 0..2047
        int r = idx >> 4, c8 = (idx & 15) * 8;
        if (z == 0 || m0 + r < cnt) {
            uint4 v = *(uint4*)&stage[r * 136 + c8];
            *(uint4*)&C[(size_t)rowC[r] * N + n0 + c8] = v;
        }
    }
}

// ---------------- K_final: STAR fusion + final MLP + sigmoid ----------------
__global__ void k_final(const float* __restrict__ fW1, const float* __restrict__ fb1,
                        const float* __restrict__ fW2, const float* __restrict__ fb2,
                        float* __restrict__ out)
{
    int r = blockIdx.x;
    int t = threadIdx.x;
    __shared__ float fs[128];
    __shared__ float red[64];
    fs[t] = __half2float(g_hc[r * 128 + t]) * tanhf(__half2float(g_hd[r * 128 + t]));
    __syncthreads();
    if (t < 64) {
        float s = fb1[t];
        #pragma unroll
        for (int j = 0; j < 128; j++) s = fmaf(fs[j], fW1[j * 64 + t], s);
        red[t] = fmaxf(s, 0.f) * fW2[t];
    }
    __syncthreads();
    if (t < 32) {
        float v = red[t] + red[t + 32];
        #pragma unroll
        for (int o = 16; o; o >>= 1) v += __shfl_down_sync(0xffffffffu, v, o);
        if (t == 0) {
            float logit = v + fb2[0] + g_aux[r];
            out[r] = 1.f / (1.f + expf(-logit));
        }
    }
}

// ---------------- launch -----------------------------------------------------
extern "C" void kernel_launch(void* const* d_in, const int* in_sizes, int n_in,
                              void* d_out, int out_size)
{
    const float* x    = (const float*)d_in[0];
    const int*   dom  = (const int*)  d_in[1];
    const float* pnw  = (const float*)d_in[2];
    const float* pnb  = (const float*)d_in[3];
    const float* demb = (const float*)d_in[4];
    const float* cw   = (const float*)d_in[5];
    const float* cb   = (const float*)d_in[6];
    const float* cW1  = (const float*)d_in[7];
    const float* cb1  = (const float*)d_in[8];
    const float* cW2  = (const float*)d_in[9];
    const float* cb2  = (const float*)d_in[10];
    const float* cW3  = (const float*)d_in[11];
    const float* cb3  = (const float*)d_in[12];
    const float* dW1  = (const float*)d_in[13];
    const float* db1  = (const float*)d_in[14];
    const float* dW2  = (const float*)d_in[15];
    const float* db2  = (const float*)d_in[16];
    const float* dW3  = (const float*)d_in[17];
    const float* db3  = (const float*)d_in[18];
    const float* fW1  = (const float*)d_in[19];
    const float* fb1  = (const float*)d_in[20];
    const float* fW2  = (const float*)d_in[21];
    const float* fb2  = (const float*)d_in[22];
    const float* aW1  = (const float*)d_in[23];
    const float* ab1  = (const float*)d_in[24];
    const float* aW2  = (const float*)d_in[25];
    const float* ab2  = (const float*)d_in[26];
    float* out = (float*)d_out;

    __half *xcP, *ch1P, *ch2P, *hcP, *dg1P, *dg2P, *hdP;
    __half *wt1cP, *wt1dP, *wt2cP, *wt2dP, *wt3cP, *wt3dP;
    cudaGetSymbolAddress((void**)&xcP,  g_xc);
    cudaGetSymbolAddress((void**)&ch1P, g_ch1);
    cudaGetSymbolAddress((void**)&ch2P, g_ch2);
    cudaGetSymbolAddress((void**)&hcP,  g_hc);
    cudaGetSymbolAddress((void**)&dg1P, g_dg1);
    cudaGetSymbolAddress((void**)&dg2P, g_dg2);
    cudaGetSymbolAddress((void**)&hdP,  g_hd);
    cudaGetSymbolAddress((void**)&wt1cP, g_wt1c);
    cudaGetSymbolAddress((void**)&wt1dP, g_wt1d);
    cudaGetSymbolAddress((void**)&wt2cP, g_wt2c);
    cudaGetSymbolAddress((void**)&wt2dP, g_wt2d);
    cudaGetSymbolAddress((void**)&wt3cP, g_wt3c);
    cudaGetSymbolAddress((void**)&wt3dP, g_wt3d);

    // weight transposes (W[K,N] fp32 -> WT[N,Kpad] half, zero-padded K)
    k_transpose<Tt,  512, K1P><<<dim3(16, K1P/32, 1),  dim3(32, 8)>>>(cW1, wt1cP);
    k_transpose<Tt,  512, K1P><<<dim3(16, K1P/32, Dd), dim3(32, 8)>>>(dW1, wt1dP);
    k_transpose<512, 256, 512><<<dim3(8,  16, 1),      dim3(32, 8)>>>(cW2, wt2cP);
    k_transpose<512, 256, 512><<<dim3(8,  16, Dd),     dim3(32, 8)>>>(dW2, wt2dP);
    k_transpose<256, 128, 256><<<dim3(4,  8, 1),       dim3(32, 8)>>>(cW3, wt3cP);
    k_transpose<256, 128, 256><<<dim3(4,  8, Dd),      dim3(32, 8)>>>(dW3, wt3dP);

    k_part<<<1, 1024>>>(dom);
    k_prep<<<Bsz, 256>>>(x, dom, pnw, pnb, demb, cw, cb, aW1, ab1, aW2, ab2);

    // layer 1: K=1056(padded) -> N=512 ; z=0 center, z=1..8 domains
    gemm_f16<K1P, 512, true,  1><<<dim3(4, 32, 9), 256>>>(xcP,  xcP,  wt1cP, wt1dP, cb1, db1, ch1P, dg1P);
    // layer 2: K=512 -> N=256
    gemm_f16<512, 256, true,  2><<<dim3(2, 32, 9), 256>>>(ch1P, dg1P, wt2cP, wt2dP, cb2, db2, ch2P, dg2P);
    // layer 3: K=256 -> N=128
    gemm_f16<256, 128, false, 3><<<dim3(1, 32, 9), 256>>>(ch2P, dg2P, wt3cP, wt3dP, cb3, db3, hcP, hdP);

    k_final<<<Bsz, 128>>>(fW1, fb1, fW2, fb2, out);
}

// round 5
// speedup vs baseline: 4.4201x; 1.0801x over previous
#include <cuda_runtime.h>
#include <cuda_fp16.h>
#include <cstdint>
#include <math.h>

#define Bsz 4096
#define Ff  1024
#define Ee  16
#define Dd  8
#define Tt  1040
#define Ll  3
#define K1P 1056   // padded K for layer 1 (multiple of 32)

// ---------------- scratch (device globals; no allocation allowed) ----------
__device__ __align__(128) __half g_xc [Bsz*K1P];
__device__ __align__(128) __half g_ch1[Bsz*512];
__device__ __align__(128) __half g_ch2[Bsz*256];
__device__ __align__(128) __half g_hc [Bsz*128];
__device__ __align__(128) __half g_dg1[Bsz*512];
__device__ __align__(128) __half g_dg2[Bsz*256];
__device__ __align__(128) __half g_hd [Bsz*128];
__device__ float g_aux[Bsz];
__device__ int   g_cnt[Dd];
__device__ int   g_off[Dd];
__device__ int   g_perm[Bsz];

// ---------------- PTX helpers ----------------------------------------------
__device__ __forceinline__ uint32_t smem_u32(const void* p) {
    uint32_t a;
    asm("{ .reg .u64 t; cvta.to.shared.u64 t, %1; cvt.u32.u64 %0, t; }" : "=r"(a) : "l"(p));
    return a;
}
__device__ __forceinline__ void ldsm4(uint32_t* r, uint32_t addr) {
    asm volatile("ldmatrix.sync.aligned.m8n8.x4.shared.b16 {%0,%1,%2,%3}, [%4];"
        : "=r"(r[0]), "=r"(r[1]), "=r"(r[2]), "=r"(r[3]) : "r"(addr));
}
__device__ __forceinline__ void ldsm4t(uint32_t* r, uint32_t addr) {
    asm volatile("ldmatrix.sync.aligned.m8n8.x4.trans.shared.b16 {%0,%1,%2,%3}, [%4];"
        : "=r"(r[0]), "=r"(r[1]), "=r"(r[2]), "=r"(r[3]) : "r"(addr));
}
__device__ __forceinline__ void mma_f16(float* c, const uint32_t* a, const uint32_t* b) {
    asm volatile("mma.sync.aligned.m16n8k16.row.col.f32.f16.f16.f32 "
        "{%0,%1,%2,%3}, {%4,%5,%6,%7}, {%8,%9}, {%0,%1,%2,%3};"
        : "+f"(c[0]), "+f"(c[1]), "+f"(c[2]), "+f"(c[3])
        : "r"(a[0]), "r"(a[1]), "r"(a[2]), "r"(a[3]), "r"(b[0]), "r"(b[1]));
}

// ---------------- block reduce ----------------------------------------------
__device__ __forceinline__ float blockReduceSum256(float v, float* red) {
    int tid = threadIdx.x;
    #pragma unroll
    for (int o = 16; o; o >>= 1) v += __shfl_down_sync(0xffffffffu, v, o);
    if ((tid & 31) == 0) red[tid >> 5] = v;
    __syncthreads();
    if (tid < 32) {
        float x = (tid < 8) ? red[tid] : 0.f;
        #pragma unroll
        for (int o = 4; o; o >>= 1) x += __shfl_down_sync(0xffffffffu, x, o);
        if (tid == 0) red[0] = x;
    }
    __syncthreads();
    float r = red[0];
    __syncthreads();
    return r;
}

// ---------------- partition: counts, offsets, permutation (one block) -------
__global__ void k_part(const int* __restrict__ dom) {
    __shared__ int scnt[Dd], soff[Dd], scur[Dd];
    int t = threadIdx.x;
    if (t < Dd) { scnt[t] = 0; scur[t] = 0; }
    __syncthreads();
    int dv[4];
    #pragma unroll
    for (int i = 0; i < 4; i++) { dv[i] = dom[t + 1024 * i]; atomicAdd(&scnt[dv[i]], 1); }
    __syncthreads();
    if (t == 0) {
        int s = 0;
        for (int d = 0; d < Dd; d++) { soff[d] = s; g_off[d] = s; g_cnt[d] = scnt[d]; s += scnt[d]; }
    }
    __syncthreads();
    #pragma unroll
    for (int i = 0; i < 4; i++) {
        int p = atomicAdd(&scur[dv[i]], 1);
        g_perm[soff[dv[i]] + p] = t + 1024 * i;
    }
}

// ---------------- K1: LayerNorm + domain affine + cross net + aux ----------
__global__ void k_prep(const float* __restrict__ x, const int* __restrict__ dom,
                       const float* __restrict__ pnw, const float* __restrict__ pnb,
                       const float* __restrict__ demb,
                       const float* __restrict__ cw, const float* __restrict__ cb,
                       const float* __restrict__ aW1, const float* __restrict__ ab1,
                       const float* __restrict__ aW2, const float* __restrict__ ab2)
{
    int r = blockIdx.x;
    int tid = threadIdx.x;
    __shared__ float s_x0[Tt];
    __shared__ float s_xc[Tt];
    __shared__ float red[32];

    const float* xr = x + (size_t)r * Ff;
    float sum = 0.f, sq = 0.f;
    for (int j = tid; j < Ff; j += 256) { float v = xr[j]; sum += v; sq += v * v; }
    float tot  = blockReduceSum256(sum, red);
    float tot2 = blockReduceSum256(sq, red);
    float mean = tot * (1.f / Ff);
    float var  = tot2 * (1.f / Ff) - mean * mean;
    float rstd = rsqrtf(var + 1e-5f);

    int d = dom[r];
    const float* wr = pnw + (size_t)d * Ff;
    const float* br = pnb + (size_t)d * Ff;
    for (int j = tid; j < Ff; j += 256) {
        float nv = (xr[j] - mean) * rstd * wr[j] + br[j];
        s_x0[j] = nv;
        s_xc[j] = nv;
    }
    for (int e = tid; e < Ee; e += 256) {
        float v = demb[d * Ee + e];
        s_x0[Ff + e] = v;
        s_xc[Ff + e] = v;
    }
    __syncthreads();

    for (int i = 0; i < Ll; i++) {
        const float* wi = cw + i * Tt;
        const float* bi = cb + i * Tt;
        float p = 0.f;
        for (int j = tid; j < Tt; j += 256) p += s_xc[j] * wi[j];
        float proj = blockReduceSum256(p, red);
        for (int j = tid; j < Tt; j += 256)
            s_xc[j] = fmaf(s_x0[j], proj, bi[j] + s_xc[j]);
        __syncthreads();
    }

    __half* out = g_xc + (size_t)r * K1P;
    for (int j = tid; j < Tt; j += 256) out[j] = __float2half_rn(s_xc[j]);
    if (tid < K1P - Tt) out[Tt + tid] = __float2half_rn(0.f);

    if (tid < 32) {
        float s = ab1[tid];
        #pragma unroll
        for (int e = 0; e < Ee; e++) s = fmaf(s_x0[Ff + e], aW1[e * 32 + tid], s);
        s = fmaxf(s, 0.f) * aW2[tid];
        #pragma unroll
        for (int o = 16; o; o >>= 1) s += __shfl_down_sync(0xffffffffu, s, o);
        if (tid == 0) g_aux[r] = s + ab2[0];
    }
}

// ---------------- fp16 tensor-core GEMM (B = original fp32 W[K,N]) ----------
// C[M,N](half) = act(A[M,K](half) @ W[K,N](fp32->half) + bias(fp32))
// z=0: center, z=1..8: domain nets. 128x128 tile, BK=32, double-buffered smem.
// A fragments via ldmatrix, B fragments via ldmatrix.trans on k-major tile.
#define BK   32
#define LDH  40                 // A smem row pitch (halfs)
#define LDB  136                // B smem row pitch (halfs)
#define ASZ  (128*LDH)          // halfs per A buffer
#define BSZ  (BK*LDB)           // halfs per B buffer
#define TILES_HALFS (2*ASZ + 2*BSZ)

template<int K, int KSRC, int N, bool RELU, int LAYER>
__global__ __launch_bounds__(256)
void gemm_f16(const __half* __restrict__ Ac, const __half* __restrict__ Ad,
              const float* __restrict__ Wc, const float* __restrict__ Wd,
              const float* __restrict__ bc, const float* __restrict__ bd,
              __half* __restrict__ Cc, __half* __restrict__ Cd)
{
    __shared__ __align__(16) __half tiles[TILES_HALFS];
    __shared__ int rowA[128], rowC[128];

    const int z  = blockIdx.z;
    const int n0 = blockIdx.x * 128;
    const int m0 = blockIdx.y * 128;

    const __half* A;
    const float *W, *bias;
    __half* C;
    int cnt;
    if (z == 0) { A = Ac; W = Wc; bias = bc; C = Cc; cnt = Bsz; }
    else {
        int d = z - 1;
        cnt = g_cnt[d];
        if (m0 >= cnt) return;
        A = Ad; W = Wd + (size_t)d * KSRC * N; bias = bd + d * N; C = Cd;
    }

    const int tid  = threadIdx.x;
    const int wid  = tid >> 5;
    const int lane = tid & 31;

    if (tid < 128) {
        if (z == 0) { rowA[tid] = m0 + tid; rowC[tid] = m0 + tid; }
        else {
            int off = g_off[z - 1];
            int mm  = min(m0 + tid, cnt - 1);
            int slot = off + mm;
            if (LAYER == 1)      { rowA[tid] = g_perm[slot]; rowC[tid] = slot; }
            else if (LAYER == 2) { rowA[tid] = slot;         rowC[tid] = slot; }
            else                 { rowA[tid] = slot;         rowC[tid] = g_perm[slot]; }
        }
    }
    __syncthreads();

    // A loader: 2 slots of 8 halfs; slot s: row = s>>2 (0..127), col8 = (s&3)*8
    const __half* aSrc[2];
    int aDst[2];
    // B loader: 2 slots of 8 floats->8 halfs; slot s: krow = s>>4 (0..31), nc8 = (s&15)*8
    int bKr[2], bDst[2];
    const float* bSrc[2];
    #pragma unroll
    for (int i = 0; i < 2; i++) {
        int s  = tid + 256 * i;
        int ar = s >> 2, ac8 = (s & 3) * 8;
        aSrc[i] = A + (size_t)rowA[ar] * K + ac8;
        aDst[i] = ar * LDH + ac8;
        int kr = s >> 4, nc8 = (s & 15) * 8;
        bKr[i]  = kr;
        bSrc[i] = W + (size_t)kr * N + n0 + nc8;
        bDst[i] = kr * LDB + nc8;
    }

    const uint32_t sbase = smem_u32(tiles);

    // fragment address components
    const int wm = (wid & 1) * 64;
    const int wn = (wid >> 1) * 32;
    const int gid = lane >> 2, tig = lane & 3;
    const uint32_t aRowOff = (uint32_t)((wm + (lane & 15)) * LDH + ((lane >> 4) * 8)) * 2;
    // B trans: lane l -> k row (l&7) + ((l>>3)&1)*8, n col wn + (l>>4)*8
    const uint32_t bAddrOff = (uint32_t)(((lane & 7) + ((lane >> 3) & 1) * 8) * LDB
                                         + wn + (lane >> 4) * 8) * 2;

    float acc[4][4][4];
    #pragma unroll
    for (int mt = 0; mt < 4; mt++)
        #pragma unroll
        for (int nt = 0; nt < 4; nt++)
            #pragma unroll
            for (int i = 0; i < 4; i++) acc[mt][nt][i] = 0.f;

    uint4 pa[2], pb[2];

    auto loadB = [&](int i, int k0) -> uint4 {
        int k = k0 + bKr[i];
        float4 f0, f1;
        if (K == KSRC || k < KSRC) {
            f0 = *(const float4*)(bSrc[i] + (size_t)k0 * N);
            f1 = *(const float4*)(bSrc[i] + (size_t)k0 * N + 4);
        } else {
            f0 = make_float4(0.f, 0.f, 0.f, 0.f);
            f1 = f0;
        }
        uint4 u;
        u.x = __half2_raw(__floats2half2_rn(f0.x, f0.y)).x | ((uint32_t)__half2_raw(__floats2half2_rn(f0.x, f0.y)).y << 16);
        // (build via union-free packing below instead)
        __half2 h0 = __floats2half2_rn(f0.x, f0.y);
        __half2 h1 = __floats2half2_rn(f0.z, f0.w);
        __half2 h2 = __floats2half2_rn(f1.x, f1.y);
        __half2 h3 = __floats2half2_rn(f1.z, f1.w);
        u.x = *(uint32_t*)&h0; u.y = *(uint32_t*)&h1;
        u.z = *(uint32_t*)&h2; u.w = *(uint32_t*)&h3;
        return u;
    };

    // prologue: chunk 0 -> buffer 0
    #pragma unroll
    for (int i = 0; i < 2; i++) {
        pa[i] = *(const uint4*)(aSrc[i]);
        pb[i] = loadB(i, 0);
        *(uint4*)(tiles + 0 * ASZ + aDst[i])       = pa[i];
        *(uint4*)(tiles + 2 * ASZ + 0 * BSZ + bDst[i]) = pb[i];
    }
    __syncthreads();

    const int NCH = K / BK;
    for (int c = 0; c < NCH; c++) {
        const int buf = c & 1;

        if (c + 1 < NCH) {
            int k0 = (c + 1) * BK;
            #pragma unroll
            for (int i = 0; i < 2; i++) {
                pa[i] = *(const uint4*)(aSrc[i] + k0);
                pb[i] = loadB(i, k0);
            }
        }

        const uint32_t aB = sbase + (uint32_t)(buf * ASZ) * 2;
        const uint32_t bB = sbase + (uint32_t)(2 * ASZ + buf * BSZ) * 2;
        #pragma unroll
        for (int kk = 0; kk < BK; kk += 16) {
            uint32_t af[4][4];
            #pragma unroll
            for (int mt = 0; mt < 4; mt++)
                ldsm4(af[mt], aB + aRowOff + (uint32_t)(mt * 16 * LDH + kk) * 2);
            #pragma unroll
            for (int ntp = 0; ntp < 2; ntp++) {
                uint32_t bf[4];
                ldsm4t(bf, bB + bAddrOff + (uint32_t)(kk * LDB + ntp * 16) * 2);
                #pragma unroll
                for (int mt = 0; mt < 4; mt++) {
                    mma_f16(acc[mt][ntp * 2 + 0], af[mt], bf + 0);
                    mma_f16(acc[mt][ntp * 2 + 1], af[mt], bf + 2);
                }
            }
        }

        if (c + 1 < NCH) {
            const int nb = buf ^ 1;
            #pragma unroll
            for (int i = 0; i < 2; i++) {
                *(uint4*)(tiles + nb * ASZ + aDst[i])            = pa[i];
                *(uint4*)(tiles + 2 * ASZ + nb * BSZ + bDst[i])  = pb[i];
            }
        }
        __syncthreads();
    }

    // epilogue: bias + act -> half, stage in smem, coalesced store
    __half* stage = tiles;      // 128 x 136 halfs = 34816 B <= TILES_HALFS*2 B
    #pragma unroll
    for (int mt = 0; mt < 4; mt++) {
        #pragma unroll
        for (int nt = 0; nt < 4; nt++) {
            int col = wn + nt * 8 + 2 * tig;
            float bx = bias[n0 + col], by = bias[n0 + col + 1];
            float v0 = acc[mt][nt][0] + bx, v1 = acc[mt][nt][1] + by;
            float v2 = acc[mt][nt][2] + bx, v3 = acc[mt][nt][3] + by;
            if (RELU) {
                v0 = fmaxf(v0, 0.f); v1 = fmaxf(v1, 0.f);
                v2 = fmaxf(v2, 0.f); v3 = fmaxf(v3, 0.f);
            }
            int r0 = wm + mt * 16 + gid;
            *(__half2*)&stage[r0 * 136 + col]       = __floats2half2_rn(v0, v1);
            *(__half2*)&stage[(r0 + 8) * 136 + col] = __floats2half2_rn(v2, v3);
        }
    }
    __syncthreads();
    #pragma unroll
    for (int i = 0; i < 8; i++) {
        int idx = tid + 256 * i;            // 0..2047
        int r = idx >> 4, c8 = (idx & 15) * 8;
        if (z == 0 || m0 + r < cnt) {
            uint4 v = *(uint4*)&stage[r * 136 + c8];
            *(uint4*)&C[(size_t)rowC[r] * N + n0 + c8] = v;
        }
    }
}

// ---------------- K_final: STAR fusion + final MLP + sigmoid ----------------
__global__ void k_final(const float* __restrict__ fW1, const float* __restrict__ fb1,
                        const float* __restrict__ fW2, const float* __restrict__ fb2,
                        float* __restrict__ out)
{
    int r = blockIdx.x;
    int t = threadIdx.x;
    __shared__ float fs[128];
    __shared__ float red[64];
    fs[t] = __half2float(g_hc[r * 128 + t]) * tanhf(__half2float(g_hd[r * 128 + t]));
    __syncthreads();
    if (t < 64) {
        float s = fb1[t];
        #pragma unroll
        for (int j = 0; j < 128; j++) s = fmaf(fs[j], fW1[j * 64 + t], s);
        red[t] = fmaxf(s, 0.f) * fW2[t];
    }
    __syncthreads();
    if (t < 32) {
        float v = red[t] + red[t + 32];
        #pragma unroll
        for (int o = 16; o; o >>= 1) v += __shfl_down_sync(0xffffffffu, v, o);
        if (t == 0) {
            float logit = v + fb2[0] + g_aux[r];
            out[r] = 1.f / (1.f + expf(-logit));
        }
    }
}

// ---------------- launch -----------------------------------------------------
extern "C" void kernel_launch(void* const* d_in, const int* in_sizes, int n_in,
                              void* d_out, int out_size)
{
    const float* x    = (const float*)d_in[0];
    const int*   dom  = (const int*)  d_in[1];
    const float* pnw  = (const float*)d_in[2];
    const float* pnb  = (const float*)d_in[3];
    const float* demb = (const float*)d_in[4];
    const float* cw   = (const float*)d_in[5];
    const float* cb   = (const float*)d_in[6];
    const float* cW1  = (const float*)d_in[7];
    const float* cb1  = (const float*)d_in[8];
    const float* cW2  = (const float*)d_in[9];
    const float* cb2  = (const float*)d_in[10];
    const float* cW3  = (const float*)d_in[11];
    const float* cb3  = (const float*)d_in[12];
    const float* dW1  = (const float*)d_in[13];
    const float* db1  = (const float*)d_in[14];
    const float* dW2  = (const float*)d_in[15];
    const float* db2  = (const float*)d_in[16];
    const float* dW3  = (const float*)d_in[17];
    const float* db3  = (const float*)d_in[18];
    const float* fW1  = (const float*)d_in[19];
    const float* fb1  = (const float*)d_in[20];
    const float* fW2  = (const float*)d_in[21];
    const float* fb2  = (const float*)d_in[22];
    const float* aW1  = (const float*)d_in[23];
    const float* ab1  = (const float*)d_in[24];
    const float* aW2  = (const float*)d_in[25];
    const float* ab2  = (const float*)d_in[26];
    float* out = (float*)d_out;

    __half *xcP, *ch1P, *ch2P, *hcP, *dg1P, *dg2P, *hdP;
    cudaGetSymbolAddress((void**)&xcP,  g_xc);
    cudaGetSymbolAddress((void**)&ch1P, g_ch1);
    cudaGetSymbolAddress((void**)&ch2P, g_ch2);
    cudaGetSymbolAddress((void**)&hcP,  g_hc);
    cudaGetSymbolAddress((void**)&dg1P, g_dg1);
    cudaGetSymbolAddress((void**)&dg2P, g_dg2);
    cudaGetSymbolAddress((void**)&hdP,  g_hd);

    k_part<<<1, 1024>>>(dom);
    k_prep<<<Bsz, 256>>>(x, dom, pnw, pnb, demb, cw, cb, aW1, ab1, aW2, ab2);

    // layer 1: K=1056(padded, src 1040) -> N=512 ; z=0 center, z=1..8 domains
    gemm_f16<K1P, Tt, 512, true,  1><<<dim3(4, 32, 9), 256>>>(xcP,  xcP,  cW1, dW1, cb1, db1, ch1P, dg1P);
    // layer 2: K=512 -> N=256
    gemm_f16<512, 512, 256, true,  2><<<dim3(2, 32, 9), 256>>>(ch1P, dg1P, cW2, dW2, cb2, db2, ch2P, dg2P);
    // layer 3: K=256 -> N=128
    gemm_f16<256, 256, 128, false, 3><<<dim3(1, 32, 9), 256>>>(ch2P, dg2P, cW3, dW3, cb3, db3, hcP, hdP);

    k_final<<<Bsz, 128>>>(fW1, fb1, fW2, fb2, out);
}

// round 6
// speedup vs baseline: 4.4987x; 1.0178x over previous
#include <cuda_runtime.h>
#include <cuda_fp16.h>
#include <cstdint>
#include <math.h>

#define Bsz 4096
#define Ff  1024
#define Ee  16
#define Dd  8
#define Tt  1040
#define Ll  3
#define K1P 1056   // padded K for layer 1 (multiple of 32)

// ---------------- scratch (device globals; no allocation allowed) ----------
__device__ __align__(128) __half g_xc [Bsz*K1P];
__device__ __align__(128) __half g_ch1[Bsz*512];
__device__ __align__(128) __half g_ch2[Bsz*256];
__device__ __align__(128) __half g_hc [Bsz*128];
__device__ __align__(128) __half g_dg1[Bsz*512];
__device__ __align__(128) __half g_dg2[Bsz*256];
__device__ __align__(128) __half g_hd [Bsz*128];
// half weights, [K(pad), N] k-major (same layout as inputs, converted once)
__device__ __align__(128) __half g_wh1c[K1P*512];
__device__ __align__(128) __half g_wh1d[Dd*K1P*512];
__device__ __align__(128) __half g_wh2c[512*256];
__device__ __align__(128) __half g_wh2d[Dd*512*256];
__device__ __align__(128) __half g_wh3c[256*128];
__device__ __align__(128) __half g_wh3d[Dd*256*128];
__device__ float g_aux[Bsz];
__device__ int   g_cnt[Dd];
__device__ int   g_off[Dd];
__device__ int   g_perm[Bsz];

// ---------------- PTX helpers ----------------------------------------------
__device__ __forceinline__ uint32_t smem_u32(const void* p) {
    uint32_t a;
    asm("{ .reg .u64 t; cvta.to.shared.u64 t, %1; cvt.u32.u64 %0, t; }" : "=r"(a) : "l"(p));
    return a;
}
__device__ __forceinline__ void ldsm4(uint32_t* r, uint32_t addr) {
    asm volatile("ldmatrix.sync.aligned.m8n8.x4.shared.b16 {%0,%1,%2,%3}, [%4];"
        : "=r"(r[0]), "=r"(r[1]), "=r"(r[2]), "=r"(r[3]) : "r"(addr));
}
__device__ __forceinline__ void ldsm4t(uint32_t* r, uint32_t addr) {
    asm volatile("ldmatrix.sync.aligned.m8n8.x4.trans.shared.b16 {%0,%1,%2,%3}, [%4];"
        : "=r"(r[0]), "=r"(r[1]), "=r"(r[2]), "=r"(r[3]) : "r"(addr));
}
__device__ __forceinline__ void mma_f16(float* c, const uint32_t* a, const uint32_t* b) {
    asm volatile("mma.sync.aligned.m16n8k16.row.col.f32.f16.f16.f32 "
        "{%0,%1,%2,%3}, {%4,%5,%6,%7}, {%8,%9}, {%0,%1,%2,%3};"
        : "+f"(c[0]), "+f"(c[1]), "+f"(c[2]), "+f"(c[3])
        : "r"(a[0]), "r"(a[1]), "r"(a[2]), "r"(a[3]), "r"(b[0]), "r"(b[1]));
}
__device__ __forceinline__ void cpa16(uint32_t dst, const void* src) {
    asm volatile("cp.async.cg.shared.global [%0], [%1], 16;" :: "r"(dst), "l"(src) : "memory");
}
#define CPA_COMMIT() asm volatile("cp.async.commit_group;" ::: "memory")
#define CPA_WAIT2()  asm volatile("cp.async.wait_group 2;" ::: "memory")

// ---------------- block reduce ----------------------------------------------
__device__ __forceinline__ float blockReduceSum256(float v, float* red) {
    int tid = threadIdx.x;
    #pragma unroll
    for (int o = 16; o; o >>= 1) v += __shfl_down_sync(0xffffffffu, v, o);
    if ((tid & 31) == 0) red[tid >> 5] = v;
    __syncthreads();
    if (tid < 32) {
        float x = (tid < 8) ? red[tid] : 0.f;
        #pragma unroll
        for (int o = 4; o; o >>= 1) x += __shfl_down_sync(0xffffffffu, x, o);
        if (tid == 0) red[0] = x;
    }
    __syncthreads();
    float r = red[0];
    __syncthreads();
    return r;
}

// ---------------- k_cvt: convert ALL weights fp32->half (pad layer1 K) ------
// segment sizes in halfs (dst):
//  wh1c: 1056*512            = 540672
//  wh1d: 8*1056*512          = 4325376   (cum 4866048)
//  wh2c: 512*256             = 131072    (cum 4997120)
//  wh2d: 8*512*256           = 1048576   (cum 6045696)
//  wh3c: 256*128             = 32768     (cum 6078464)
//  wh3d: 8*256*128           = 262144    (cum 6340608)
#define CVT_TOTAL 6340608
#define CVT_BLOCKS 3096        // 3096*256*8 == CVT_TOTAL

__global__ void k_cvt(const float* __restrict__ cW1, const float* __restrict__ dW1,
                      const float* __restrict__ cW2, const float* __restrict__ dW2,
                      const float* __restrict__ cW3, const float* __restrict__ dW3)
{
    size_t idx = ((size_t)blockIdx.x * 256 + threadIdx.x) * 8;
    const float* src; __half* dst;
    int KIN, KPAD, N;
    size_t off;
    if      (idx < 540672)  { src = cW1; dst = g_wh1c; KIN = Tt;  KPAD = K1P; N = 512; off = idx; }
    else if (idx < 4866048) { src = dW1; dst = g_wh1d; KIN = Tt;  KPAD = K1P; N = 512; off = idx - 540672; }
    else if (idx < 4997120) { src = cW2; dst = g_wh2c; KIN = 512; KPAD = 512; N = 256; off = idx - 4866048; }
    else if (idx < 6045696) { src = dW2; dst = g_wh2d; KIN = 512; KPAD = 512; N = 256; off = idx - 4997120; }
    else if (idx < 6078464) { src = cW3; dst = g_wh3c; KIN = 256; KPAD = 256; N = 128; off = idx - 6045696; }
    else                    { src = dW3; dst = g_wh3d; KIN = 256; KPAD = 256; N = 128; off = idx - 6078464; }

    size_t per = (size_t)KPAD * N;
    int d = (int)(off / per);
    size_t r = off % per;
    int k = (int)(r / N), n = (int)(r % N);
    uint4 u;
    if (k < KIN) {
        const float* s = src + ((size_t)d * KIN + k) * N + n;
        float4 f0 = *(const float4*)s;
        float4 f1 = *(const float4*)(s + 4);
        __half2 h0 = __floats2half2_rn(f0.x, f0.y), h1 = __floats2half2_rn(f0.z, f0.w);
        __half2 h2 = __floats2half2_rn(f1.x, f1.y), h3 = __floats2half2_rn(f1.z, f1.w);
        u.x = *(uint32_t*)&h0; u.y = *(uint32_t*)&h1;
        u.z = *(uint32_t*)&h2; u.w = *(uint32_t*)&h3;
    } else {
        u = make_uint4(0, 0, 0, 0);
    }
    *(uint4*)(dst + off) = u;
}

// ---------------- partition: counts, offsets, permutation (one block) -------
__global__ void k_part(const int* __restrict__ dom) {
    __shared__ int scnt[Dd], soff[Dd], scur[Dd];
    int t = threadIdx.x;
    if (t < Dd) { scnt[t] = 0; scur[t] = 0; }
    __syncthreads();
    int dv[4];
    #pragma unroll
    for (int i = 0; i < 4; i++) { dv[i] = dom[t + 1024 * i]; atomicAdd(&scnt[dv[i]], 1); }
    __syncthreads();
    if (t == 0) {
        int s = 0;
        for (int d = 0; d < Dd; d++) { soff[d] = s; g_off[d] = s; g_cnt[d] = scnt[d]; s += scnt[d]; }
    }
    __syncthreads();
    #pragma unroll
    for (int i = 0; i < 4; i++) {
        int p = atomicAdd(&scur[dv[i]], 1);
        g_perm[soff[dv[i]] + p] = t + 1024 * i;
    }
}

// ---------------- k_prep: LayerNorm + domain affine + cross net + aux -------
__global__ void k_prep(const float* __restrict__ x, const int* __restrict__ dom,
                       const float* __restrict__ pnw, const float* __restrict__ pnb,
                       const float* __restrict__ demb,
                       const float* __restrict__ cw, const float* __restrict__ cb,
                       const float* __restrict__ aW1, const float* __restrict__ ab1,
                       const float* __restrict__ aW2, const float* __restrict__ ab2)
{
    int r = blockIdx.x;
    int tid = threadIdx.x;
    __shared__ float s_x0[Tt];
    __shared__ float s_xc[Tt];
    __shared__ float red[32];

    const float* xr = x + (size_t)r * Ff;
    float sum = 0.f, sq = 0.f;
    for (int j = tid; j < Ff; j += 256) { float v = xr[j]; sum += v; sq += v * v; }
    float tot  = blockReduceSum256(sum, red);
    float tot2 = blockReduceSum256(sq, red);
    float mean = tot * (1.f / Ff);
    float var  = tot2 * (1.f / Ff) - mean * mean;
    float rstd = rsqrtf(var + 1e-5f);

    int d = dom[r];
    const float* wr = pnw + (size_t)d * Ff;
    const float* br = pnb + (size_t)d * Ff;
    for (int j = tid; j < Ff; j += 256) {
        float nv = (xr[j] - mean) * rstd * wr[j] + br[j];
        s_x0[j] = nv;
        s_xc[j] = nv;
    }
    for (int e = tid; e < Ee; e += 256) {
        float v = demb[d * Ee + e];
        s_x0[Ff + e] = v;
        s_xc[Ff + e] = v;
    }
    __syncthreads();

    for (int i = 0; i < Ll; i++) {
        const float* wi = cw + i * Tt;
        const float* bi = cb + i * Tt;
        float p = 0.f;
        for (int j = tid; j < Tt; j += 256) p += s_xc[j] * wi[j];
        float proj = blockReduceSum256(p, red);
        for (int j = tid; j < Tt; j += 256)
            s_xc[j] = fmaf(s_x0[j], proj, bi[j] + s_xc[j]);
        __syncthreads();
    }

    __half* out = g_xc + (size_t)r * K1P;
    for (int j = tid; j < Tt; j += 256) out[j] = __float2half_rn(s_xc[j]);
    if (tid < K1P - Tt) out[Tt + tid] = __float2half_rn(0.f);

    if (tid < 32) {
        float s = ab1[tid];
        #pragma unroll
        for (int e = 0; e < Ee; e++) s = fmaf(s_x0[Ff + e], aW1[e * 32 + tid], s);
        s = fmaxf(s, 0.f) * aW2[tid];
        #pragma unroll
        for (int o = 16; o; o >>= 1) s += __shfl_down_sync(0xffffffffu, s, o);
        if (tid == 0) g_aux[r] = s + ab2[0];
    }
}

// ---------------- fp16 tensor-core GEMM, cp.async 4-stage pipeline ----------
// C[M,N](half) = act(A[M,K](half) @ W[K,N](half) + bias(fp32))
// z=0: center, z=1..8: domain nets. 128x128 tile, BK=32.
#define BK     32
#define LDH    40                 // A smem row pitch (halfs)
#define LDB    136                // B smem row pitch (halfs)
#define ASZ    (128*LDH)          // halfs per A stage (5120)
#define BSZ    (BK*LDB)           // halfs per B stage (4352)
#define STAGES 4
#define DYNSM  (STAGES*(ASZ+BSZ)*2)   // 75776 bytes

template<int K, int N, bool RELU, int LAYER>
__global__ __launch_bounds__(256)
void gemm_f16(const __half* __restrict__ Ac, const __half* __restrict__ Ad,
              const __half* __restrict__ Wc, const __half* __restrict__ Wd,
              const float* __restrict__ bc, const float* __restrict__ bd,
              __half* __restrict__ Cc, __half* __restrict__ Cd)
{
    extern __shared__ __align__(16) __half tiles[];
    __shared__ int rowA[128], rowC[128];

    const int z  = blockIdx.z;
    const int n0 = blockIdx.x * 128;
    const int m0 = blockIdx.y * 128;

    const __half *A, *W;
    const float* bias;
    __half* C;
    int cnt;
    if (z == 0) { A = Ac; W = Wc; bias = bc; C = Cc; cnt = Bsz; }
    else {
        int d = z - 1;
        cnt = g_cnt[d];
        if (m0 >= cnt) return;
        A = Ad; W = Wd + (size_t)d * K * N; bias = bd + d * N; C = Cd;
    }

    const int tid  = threadIdx.x;
    const int wid  = tid >> 5;
    const int lane = tid & 31;

    if (tid < 128) {
        if (z == 0) { rowA[tid] = m0 + tid; rowC[tid] = m0 + tid; }
        else {
            int off = g_off[z - 1];
            int mm  = min(m0 + tid, cnt - 1);
            int slot = off + mm;
            if (LAYER == 1)      { rowA[tid] = g_perm[slot]; rowC[tid] = slot; }
            else if (LAYER == 2) { rowA[tid] = slot;         rowC[tid] = slot; }
            else                 { rowA[tid] = slot;         rowC[tid] = g_perm[slot]; }
        }
    }
    __syncthreads();

    // loader mapping: per thread 2 A slots + 2 B slots, 16B each
    const __half* aSrc[2];
    const __half* bSrc[2];
    uint32_t aDst[2], bDst[2];
    #pragma unroll
    for (int i = 0; i < 2; i++) {
        int s  = tid + 256 * i;
        int ar = s >> 2, ac8 = (s & 3) * 8;
        aSrc[i] = A + (size_t)rowA[ar] * K + ac8;
        aDst[i] = (uint32_t)(ar * LDH + ac8) * 2;
        int kr = s >> 4, nc8 = (s & 15) * 8;
        bSrc[i] = W + (size_t)kr * N + n0 + nc8;
        bDst[i] = (uint32_t)(kr * LDB + nc8) * 2;
    }

    const uint32_t sbase = smem_u32(tiles);

    // fragment address components
    const int wm = (wid & 1) * 64;
    const int wn = (wid >> 1) * 32;
    const int gid = lane >> 2, tig = lane & 3;
    const uint32_t aRowOff = (uint32_t)((wm + (lane & 15)) * LDH + ((lane >> 4) * 8)) * 2;
    const uint32_t bAddrOff = (uint32_t)(((lane & 7) + ((lane >> 3) & 1) * 8) * LDB
                                         + wn + (lane >> 4) * 8) * 2;

    float acc[4][4][4];
    #pragma unroll
    for (int mt = 0; mt < 4; mt++)
        #pragma unroll
        for (int nt = 0; nt < 4; nt++)
            #pragma unroll
            for (int i = 0; i < 4; i++) acc[mt][nt][i] = 0.f;

    const int NCH = K / BK;

    auto issue = [&](int c, int st) {
        uint32_t aS = sbase + (uint32_t)(st * ASZ) * 2;
        uint32_t bS = sbase + (uint32_t)(STAGES * ASZ + st * BSZ) * 2;
        int k0 = c * BK;
        #pragma unroll
        for (int i = 0; i < 2; i++) cpa16(aS + aDst[i], aSrc[i] + k0);
        #pragma unroll
        for (int i = 0; i < 2; i++) cpa16(bS + bDst[i], bSrc[i] + (size_t)k0 * N);
    };

    // prologue: chunks 0..STAGES-2
    #pragma unroll
    for (int s = 0; s < STAGES - 1; s++) {
        issue(s, s);
        CPA_COMMIT();
    }

    for (int c = 0; c < NCH; c++) {
        CPA_WAIT2();
        __syncthreads();
        if (c + STAGES - 1 < NCH) issue(c + STAGES - 1, (c + STAGES - 1) & (STAGES - 1));
        CPA_COMMIT();

        const int st = c & (STAGES - 1);
        const uint32_t aB = sbase + (uint32_t)(st * ASZ) * 2;
        const uint32_t bB = sbase + (uint32_t)(STAGES * ASZ + st * BSZ) * 2;
        #pragma unroll
        for (int kk = 0; kk < BK; kk += 16) {
            uint32_t af[4][4];
            #pragma unroll
            for (int mt = 0; mt < 4; mt++)
                ldsm4(af[mt], aB + aRowOff + (uint32_t)(mt * 16 * LDH + kk) * 2);
            #pragma unroll
            for (int ntp = 0; ntp < 2; ntp++) {
                uint32_t bf[4];
                ldsm4t(bf, bB + bAddrOff + (uint32_t)(kk * LDB + ntp * 16) * 2);
                #pragma unroll
                for (int mt = 0; mt < 4; mt++) {
                    mma_f16(acc[mt][ntp * 2 + 0], af[mt], bf + 0);
                    mma_f16(acc[mt][ntp * 2 + 1], af[mt], bf + 2);
                }
            }
        }
    }
    __syncthreads();

    // epilogue: bias + act -> half, stage in smem, coalesced store
    __half* stage = tiles;      // 128 x 136 halfs = 34816 B < DYNSM
    #pragma unroll
    for (int mt = 0; mt < 4; mt++) {
        #pragma unroll
        for (int nt = 0; nt < 4; nt++) {
            int col = wn + nt * 8 + 2 * tig;
            float bx = bias[n0 + col], by = bias[n0 + col + 1];
            float v0 = acc[mt][nt][0] + bx, v1 = acc[mt][nt][1] + by;
            float v2 = acc[mt][nt][2] + bx, v3 = acc[mt][nt][3] + by;
            if (RELU) {
                v0 = fmaxf(v0, 0.f); v1 = fmaxf(v1, 0.f);
                v2 = fmaxf(v2, 0.f); v3 = fmaxf(v3, 0.f);
            }
            int r0 = wm + mt * 16 + gid;
            *(__half2*)&stage[r0 * 136 + col]       = __floats2half2_rn(v0, v1);
            *(__half2*)&stage[(r0 + 8) * 136 + col] = __floats2half2_rn(v2, v3);
        }
    }
    __syncthreads();
    #pragma unroll
    for (int i = 0; i < 8; i++) {
        int idx = tid + 256 * i;            // 0..2047
        int r = idx >> 4, c8 = (idx & 15) * 8;
        if (z == 0 || m0 + r < cnt) {
            uint4 v = *(uint4*)&stage[r * 136 + c8];
            *(uint4*)&C[(size_t)rowC[r] * N + n0 + c8] = v;
        }
    }
}

// ---------------- K_final: STAR fusion + final MLP + sigmoid ----------------
__global__ void k_final(const float* __restrict__ fW1, const float* __restrict__ fb1,
                        const float* __restrict__ fW2, const float* __restrict__ fb2,
                        float* __restrict__ out)
{
    int r = blockIdx.x;
    int t = threadIdx.x;
    __shared__ float fs[128];
    __shared__ float red[64];
    fs[t] = __half2float(g_hc[r * 128 + t]) * tanhf(__half2float(g_hd[r * 128 + t]));
    __syncthreads();
    if (t < 64) {
        float s = fb1[t];
        #pragma unroll
        for (int j = 0; j < 128; j++) s = fmaf(fs[j], fW1[j * 64 + t], s);
        red[t] = fmaxf(s, 0.f) * fW2[t];
    }
    __syncthreads();
    if (t < 32) {
        float v = red[t] + red[t + 32];
        #pragma unroll
        for (int o = 16; o; o >>= 1) v += __shfl_down_sync(0xffffffffu, v, o);
        if (t == 0) {
            float logit = v + fb2[0] + g_aux[r];
            out[r] = 1.f / (1.f + expf(-logit));
        }
    }
}

// ---------------- launch -----------------------------------------------------
extern "C" void kernel_launch(void* const* d_in, const int* in_sizes, int n_in,
                              void* d_out, int out_size)
{
    const float* x    = (const float*)d_in[0];
    const int*   dom  = (const int*)  d_in[1];
    const float* pnw  = (const float*)d_in[2];
    const float* pnb  = (const float*)d_in[3];
    const float* demb = (const float*)d_in[4];
    const float* cw   = (const float*)d_in[5];
    const float* cb   = (const float*)d_in[6];
    const float* cW1  = (const float*)d_in[7];
    const float* cb1  = (const float*)d_in[8];
    const float* cW2  = (const float*)d_in[9];
    const float* cb2  = (const float*)d_in[10];
    const float* cW3  = (const float*)d_in[11];
    const float* cb3  = (const float*)d_in[12];
    const float* dW1  = (const float*)d_in[13];
    const float* db1  = (const float*)d_in[14];
    const float* dW2  = (const float*)d_in[15];
    const float* db2  = (const float*)d_in[16];
    const float* dW3  = (const float*)d_in[17];
    const float* db3  = (const float*)d_in[18];
    const float* fW1  = (const float*)d_in[19];
    const float* fb1  = (const float*)d_in[20];
    const float* fW2  = (const float*)d_in[21];
    const float* fb2  = (const float*)d_in[22];
    const float* aW1  = (const float*)d_in[23];
    const float* ab1  = (const float*)d_in[24];
    const float* aW2  = (const float*)d_in[25];
    const float* ab2  = (const float*)d_in[26];
    float* out = (float*)d_out;

    __half *xcP, *ch1P, *ch2P, *hcP, *dg1P, *dg2P, *hdP;
    __half *wh1cP, *wh1dP, *wh2cP, *wh2dP, *wh3cP, *wh3dP;
    cudaGetSymbolAddress((void**)&xcP,  g_xc);
    cudaGetSymbolAddress((void**)&ch1P, g_ch1);
    cudaGetSymbolAddress((void**)&ch2P, g_ch2);
    cudaGetSymbolAddress((void**)&hcP,  g_hc);
    cudaGetSymbolAddress((void**)&dg1P, g_dg1);
    cudaGetSymbolAddress((void**)&dg2P, g_dg2);
    cudaGetSymbolAddress((void**)&hdP,  g_hd);
    cudaGetSymbolAddress((void**)&wh1cP, g_wh1c);
    cudaGetSymbolAddress((void**)&wh1dP, g_wh1d);
    cudaGetSymbolAddress((void**)&wh2cP, g_wh2c);
    cudaGetSymbolAddress((void**)&wh2dP, g_wh2d);
    cudaGetSymbolAddress((void**)&wh3cP, g_wh3c);
    cudaGetSymbolAddress((void**)&wh3dP, g_wh3d);

    cudaFuncSetAttribute(gemm_f16<K1P, 512, true,  1>, cudaFuncAttributeMaxDynamicSharedMemorySize, DYNSM);
    cudaFuncSetAttribute(gemm_f16<512, 256, true,  2>, cudaFuncAttributeMaxDynamicSharedMemorySize, DYNSM);
    cudaFuncSetAttribute(gemm_f16<256, 128, false, 3>, cudaFuncAttributeMaxDynamicSharedMemorySize, DYNSM);

    k_cvt<<<CVT_BLOCKS, 256>>>(cW1, dW1, cW2, dW2, cW3, dW3);
    k_part<<<1, 1024>>>(dom);
    k_prep<<<Bsz, 256>>>(x, dom, pnw, pnb, demb, cw, cb, aW1, ab1, aW2, ab2);

    // layer 1: K=1056(padded) -> N=512 ; z=0 center, z=1..8 domains
    gemm_f16<K1P, 512, true,  1><<<dim3(4, 32, 9), 256, DYNSM>>>(xcP,  xcP,  wh1cP, wh1dP, cb1, db1, ch1P, dg1P);
    // layer 2: K=512 -> N=256
    gemm_f16<512, 256, true,  2><<<dim3(2, 32, 9), 256, DYNSM>>>(ch1P, dg1P, wh2cP, wh2dP, cb2, db2, ch2P, dg2P);
    // layer 3: K=256 -> N=128
    gemm_f16<256, 128, false, 3><<<dim3(1, 32, 9), 256, DYNSM>>>(ch2P, dg2P, wh3cP, wh3dP, cb3, db3, hcP, hdP);

    k_final<<<Bsz, 128>>>(fW1, fb1, fW2, fb2, out);
}

// round 7
// speedup vs baseline: 4.7170x; 1.0485x over previous
#include <cuda_runtime.h>
#include <cuda_fp16.h>
#include <cstdint>
#include <math.h>

#define Bsz 4096
#define Ff  1024
#define Ee  16
#define Dd  8
#define Tt  1040
#define Ll  3
#define K1P 1088   // padded K for layer 1 (multiple of 64)

// ---------------- scratch (device globals; no allocation allowed) ----------
__device__ __align__(128) __half g_xc [Bsz*K1P];
__device__ __align__(128) __half g_ch1[Bsz*512];
__device__ __align__(128) __half g_ch2[Bsz*256];
__device__ __align__(128) __half g_hc [Bsz*128];
__device__ __align__(128) __half g_dg1[Bsz*512];
__device__ __align__(128) __half g_dg2[Bsz*256];
__device__ __align__(128) __half g_hd [Bsz*128];
// half weights, [K(pad), N] k-major (same layout as inputs, converted once)
__device__ __align__(128) __half g_wh1c[K1P*512];
__device__ __align__(128) __half g_wh1d[Dd*K1P*512];
__device__ __align__(128) __half g_wh2c[512*256];
__device__ __align__(128) __half g_wh2d[Dd*512*256];
__device__ __align__(128) __half g_wh3c[256*128];
__device__ __align__(128) __half g_wh3d[Dd*256*128];
__device__ float g_aux[Bsz];
__device__ int   g_cnt[Dd];
__device__ int   g_off[Dd];
__device__ int   g_perm[Bsz];

// ---------------- PTX helpers ----------------------------------------------
__device__ __forceinline__ uint32_t smem_u32(const void* p) {
    uint32_t a;
    asm("{ .reg .u64 t; cvta.to.shared.u64 t, %1; cvt.u32.u64 %0, t; }" : "=r"(a) : "l"(p));
    return a;
}
__device__ __forceinline__ void ldsm4(uint32_t* r, uint32_t addr) {
    asm volatile("ldmatrix.sync.aligned.m8n8.x4.shared.b16 {%0,%1,%2,%3}, [%4];"
        : "=r"(r[0]), "=r"(r[1]), "=r"(r[2]), "=r"(r[3]) : "r"(addr));
}
__device__ __forceinline__ void ldsm4t(uint32_t* r, uint32_t addr) {
    asm volatile("ldmatrix.sync.aligned.m8n8.x4.trans.shared.b16 {%0,%1,%2,%3}, [%4];"
        : "=r"(r[0]), "=r"(r[1]), "=r"(r[2]), "=r"(r[3]) : "r"(addr));
}
__device__ __forceinline__ void mma_f16(float* c, const uint32_t* a, const uint32_t* b) {
    asm volatile("mma.sync.aligned.m16n8k16.row.col.f32.f16.f16.f32 "
        "{%0,%1,%2,%3}, {%4,%5,%6,%7}, {%8,%9}, {%0,%1,%2,%3};"
        : "+f"(c[0]), "+f"(c[1]), "+f"(c[2]), "+f"(c[3])
        : "r"(a[0]), "r"(a[1]), "r"(a[2]), "r"(a[3]), "r"(b[0]), "r"(b[1]));
}
__device__ __forceinline__ void cpa16(uint32_t dst, const void* src) {
    asm volatile("cp.async.cg.shared.global [%0], [%1], 16;" :: "r"(dst), "l"(src) : "memory");
}
#define CPA_COMMIT() asm volatile("cp.async.commit_group;" ::: "memory")
#define CPA_WAIT1()  asm volatile("cp.async.wait_group 1;" ::: "memory")

// ---------------- block reduce ----------------------------------------------
__device__ __forceinline__ float blockReduceSum256(float v, float* red) {
    int tid = threadIdx.x;
    #pragma unroll
    for (int o = 16; o; o >>= 1) v += __shfl_down_sync(0xffffffffu, v, o);
    if ((tid & 31) == 0) red[tid >> 5] = v;
    __syncthreads();
    if (tid < 32) {
        float x = (tid < 8) ? red[tid] : 0.f;
        #pragma unroll
        for (int o = 4; o; o >>= 1) x += __shfl_down_sync(0xffffffffu, x, o);
        if (tid == 0) red[0] = x;
    }
    __syncthreads();
    float r = red[0];
    __syncthreads();
    return r;
}

// ---------------- k_cvt: convert ALL weights fp32->half (pad layer1 K) ------
// segment sizes in halfs (dst):
//  wh1c: 1088*512            = 557056
//  wh1d: 8*1088*512          = 4456448   (cum 5013504)
//  wh2c: 512*256             = 131072    (cum 5144576)
//  wh2d: 8*512*256           = 1048576   (cum 6193152)
//  wh3c: 256*128             = 32768     (cum 6225920)
//  wh3d: 8*256*128           = 262144    (cum 6488064)
#define CVT_TOTAL 6488064
#define CVT_BLOCKS 3168        // 3168*256*8 == CVT_TOTAL

__global__ void k_cvt(const float* __restrict__ cW1, const float* __restrict__ dW1,
                      const float* __restrict__ cW2, const float* __restrict__ dW2,
                      const float* __restrict__ cW3, const float* __restrict__ dW3)
{
    size_t idx = ((size_t)blockIdx.x * 256 + threadIdx.x) * 8;
    const float* src; __half* dst;
    int KIN, KPAD, N;
    size_t off;
    if      (idx < 557056)  { src = cW1; dst = g_wh1c; KIN = Tt;  KPAD = K1P; N = 512; off = idx; }
    else if (idx < 5013504) { src = dW1; dst = g_wh1d; KIN = Tt;  KPAD = K1P; N = 512; off = idx - 557056; }
    else if (idx < 5144576) { src = cW2; dst = g_wh2c; KIN = 512; KPAD = 512; N = 256; off = idx - 5013504; }
    else if (idx < 6193152) { src = dW2; dst = g_wh2d; KIN = 512; KPAD = 512; N = 256; off = idx - 5144576; }
    else if (idx < 6225920) { src = cW3; dst = g_wh3c; KIN = 256; KPAD = 256; N = 128; off = idx - 6193152; }
    else                    { src = dW3; dst = g_wh3d; KIN = 256; KPAD = 256; N = 128; off = idx - 6225920; }

    size_t per = (size_t)KPAD * N;
    int d = (int)(off / per);
    size_t r = off % per;
    int k = (int)(r / N), n = (int)(r % N);
    uint4 u;
    if (k < KIN) {
        const float* s = src + ((size_t)d * KIN + k) * N + n;
        float4 f0 = *(const float4*)s;
        float4 f1 = *(const float4*)(s + 4);
        __half2 h0 = __floats2half2_rn(f0.x, f0.y), h1 = __floats2half2_rn(f0.z, f0.w);
        __half2 h2 = __floats2half2_rn(f1.x, f1.y), h3 = __floats2half2_rn(f1.z, f1.w);
        u.x = *(uint32_t*)&h0; u.y = *(uint32_t*)&h1;
        u.z = *(uint32_t*)&h2; u.w = *(uint32_t*)&h3;
    } else {
        u = make_uint4(0, 0, 0, 0);
    }
    *(uint4*)(dst + off) = u;
}

// ---------------- partition: counts, offsets, permutation (one block) -------
__global__ void k_part(const int* __restrict__ dom) {
    __shared__ int scnt[Dd], soff[Dd], scur[Dd];
    int t = threadIdx.x;
    if (t < Dd) { scnt[t] = 0; scur[t] = 0; }
    __syncthreads();
    int dv[4];
    #pragma unroll
    for (int i = 0; i < 4; i++) { dv[i] = dom[t + 1024 * i]; atomicAdd(&scnt[dv[i]], 1); }
    __syncthreads();
    if (t == 0) {
        int s = 0;
        for (int d = 0; d < Dd; d++) { soff[d] = s; g_off[d] = s; g_cnt[d] = scnt[d]; s += scnt[d]; }
    }
    __syncthreads();
    #pragma unroll
    for (int i = 0; i < 4; i++) {
        int p = atomicAdd(&scur[dv[i]], 1);
        g_perm[soff[dv[i]] + p] = t + 1024 * i;
    }
}

// ---------------- k_prep: LayerNorm + domain affine + cross net + aux -------
__global__ void k_prep(const float* __restrict__ x, const int* __restrict__ dom,
                       const float* __restrict__ pnw, const float* __restrict__ pnb,
                       const float* __restrict__ demb,
                       const float* __restrict__ cw, const float* __restrict__ cb,
                       const float* __restrict__ aW1, const float* __restrict__ ab1,
                       const float* __restrict__ aW2, const float* __restrict__ ab2)
{
    int r = blockIdx.x;
    int tid = threadIdx.x;
    __shared__ float s_x0[Tt];
    __shared__ float s_xc[Tt];
    __shared__ float red[32];

    const float* xr = x + (size_t)r * Ff;
    float sum = 0.f, sq = 0.f;
    for (int j = tid; j < Ff; j += 256) { float v = xr[j]; sum += v; sq += v * v; }
    float tot  = blockReduceSum256(sum, red);
    float tot2 = blockReduceSum256(sq, red);
    float mean = tot * (1.f / Ff);
    float var  = tot2 * (1.f / Ff) - mean * mean;
    float rstd = rsqrtf(var + 1e-5f);

    int d = dom[r];
    const float* wr = pnw + (size_t)d * Ff;
    const float* br = pnb + (size_t)d * Ff;
    for (int j = tid; j < Ff; j += 256) {
        float nv = (xr[j] - mean) * rstd * wr[j] + br[j];
        s_x0[j] = nv;
        s_xc[j] = nv;
    }
    for (int e = tid; e < Ee; e += 256) {
        float v = demb[d * Ee + e];
        s_x0[Ff + e] = v;
        s_xc[Ff + e] = v;
    }
    __syncthreads();

    for (int i = 0; i < Ll; i++) {
        const float* wi = cw + i * Tt;
        const float* bi = cb + i * Tt;
        float p = 0.f;
        for (int j = tid; j < Tt; j += 256) p += s_xc[j] * wi[j];
        float proj = blockReduceSum256(p, red);
        for (int j = tid; j < Tt; j += 256)
            s_xc[j] = fmaf(s_x0[j], proj, bi[j] + s_xc[j]);
        __syncthreads();
    }

    __half* out = g_xc + (size_t)r * K1P;
    for (int j = tid; j < Tt; j += 256) out[j] = __float2half_rn(s_xc[j]);
    if (tid < K1P - Tt) out[Tt + tid] = __float2half_rn(0.f);

    if (tid < 32) {
        float s = ab1[tid];
        #pragma unroll
        for (int e = 0; e < Ee; e++) s = fmaf(s_x0[Ff + e], aW1[e * 32 + tid], s);
        s = fmaxf(s, 0.f) * aW2[tid];
        #pragma unroll
        for (int o = 16; o; o >>= 1) s += __shfl_down_sync(0xffffffffu, s, o);
        if (tid == 0) g_aux[r] = s + ab2[0];
    }
}

// ---------------- fp16 tensor-core GEMM, cp.async 3-stage, BK=64 ------------
// C[M,N](half) = act(A[M,K](half) @ W[K,N](half) + bias(fp32))
// z=0: center, z=1..8: domain nets. 128x128 tile.
#define BK     64
#define LDH    72                 // A smem row pitch (halfs): 64 + 8
#define LDB    136                // B smem row pitch (halfs)
#define ASZ    (128*LDH)          // halfs per A stage (9216)
#define BSZ    (BK*LDB)           // halfs per B stage (8704)
#define STAGES 3
#define DYNSM  (STAGES*(ASZ+BSZ)*2)   // 107520 bytes

template<int K, int N, bool RELU, int LAYER>
__global__ __launch_bounds__(256, 2)
void gemm_f16(const __half* __restrict__ Ac, const __half* __restrict__ Ad,
              const __half* __restrict__ Wc, const __half* __restrict__ Wd,
              const float* __restrict__ bc, const float* __restrict__ bd,
              __half* __restrict__ Cc, __half* __restrict__ Cd)
{
    extern __shared__ __align__(16) __half tiles[];
    __shared__ int rowA[128], rowC[128];

    const int z  = blockIdx.z;
    const int n0 = blockIdx.x * 128;
    const int m0 = blockIdx.y * 128;

    const __half *A, *W;
    const float* bias;
    __half* C;
    int cnt;
    if (z == 0) { A = Ac; W = Wc; bias = bc; C = Cc; cnt = Bsz; }
    else {
        int d = z - 1;
        cnt = g_cnt[d];
        if (m0 >= cnt) return;
        A = Ad; W = Wd + (size_t)d * K * N; bias = bd + d * N; C = Cd;
    }

    const int tid  = threadIdx.x;
    const int wid  = tid >> 5;
    const int lane = tid & 31;

    if (tid < 128) {
        if (z == 0) { rowA[tid] = m0 + tid; rowC[tid] = m0 + tid; }
        else {
            int off = g_off[z - 1];
            int mm  = min(m0 + tid, cnt - 1);
            int slot = off + mm;
            if (LAYER == 1)      { rowA[tid] = g_perm[slot]; rowC[tid] = slot; }
            else if (LAYER == 2) { rowA[tid] = slot;         rowC[tid] = slot; }
            else                 { rowA[tid] = slot;         rowC[tid] = g_perm[slot]; }
        }
    }
    __syncthreads();

    // loader mapping: per thread 4 A slots + 4 B slots, 16B each per chunk
    const __half* aSrc[4];
    const __half* bSrc[4];
    uint32_t aDst[4], bDst[4];
    #pragma unroll
    for (int i = 0; i < 4; i++) {
        int s  = tid + 256 * i;              // 0..1023
        int ar = s >> 3, ac8 = (s & 7) * 8;  // row 0..127, k-col8 0..56
        aSrc[i] = A + (size_t)rowA[ar] * K + ac8;
        aDst[i] = (uint32_t)(ar * LDH + ac8) * 2;
        int kr = s >> 4, nc8 = (s & 15) * 8; // krow 0..63, ncol8 0..120
        bSrc[i] = W + (size_t)kr * N + n0 + nc8;
        bDst[i] = (uint32_t)(kr * LDB + nc8) * 2;
    }

    const uint32_t sbase = smem_u32(tiles);

    // fragment address components
    const int wm = (wid & 1) * 64;
    const int wn = (wid >> 1) * 32;
    const int gid = lane >> 2, tig = lane & 3;
    const uint32_t aRowOff = (uint32_t)((wm + (lane & 15)) * LDH + ((lane >> 4) * 8)) * 2;
    const uint32_t bAddrOff = (uint32_t)(((lane & 7) + ((lane >> 3) & 1) * 8) * LDB
                                         + wn + (lane >> 4) * 8) * 2;

    float acc[4][4][4];
    #pragma unroll
    for (int mt = 0; mt < 4; mt++)
        #pragma unroll
        for (int nt = 0; nt < 4; nt++)
            #pragma unroll
            for (int i = 0; i < 4; i++) acc[mt][nt][i] = 0.f;

    const int NCH = K / BK;

    auto issue = [&](int c, int st) {
        uint32_t aS = sbase + (uint32_t)(st * ASZ) * 2;
        uint32_t bS = sbase + (uint32_t)(STAGES * ASZ + st * BSZ) * 2;
        int k0 = c * BK;
        #pragma unroll
        for (int i = 0; i < 4; i++) cpa16(aS + aDst[i], aSrc[i] + k0);
        #pragma unroll
        for (int i = 0; i < 4; i++) cpa16(bS + bDst[i], bSrc[i] + (size_t)k0 * N);
    };

    // prologue: chunks 0,1 -> stages 0,1
    issue(0, 0); CPA_COMMIT();
    issue(1, 1); CPA_COMMIT();

    for (int c = 0; c < NCH; c++) {
        CPA_WAIT1();
        __syncthreads();
        if (c + 2 < NCH) issue(c + 2, (c + 2) % STAGES);
        CPA_COMMIT();

        const int st = c % STAGES;
        const uint32_t aB = sbase + (uint32_t)(st * ASZ) * 2;
        const uint32_t bB = sbase + (uint32_t)(STAGES * ASZ + st * BSZ) * 2;
        #pragma unroll
        for (int kk = 0; kk < BK; kk += 16) {
            uint32_t af[4][4];
            #pragma unroll
            for (int mt = 0; mt < 4; mt++)
                ldsm4(af[mt], aB + aRowOff + (uint32_t)(mt * 16 * LDH + kk) * 2);
            #pragma unroll
            for (int ntp = 0; ntp < 2; ntp++) {
                uint32_t bf[4];
                ldsm4t(bf, bB + bAddrOff + (uint32_t)(kk * LDB + ntp * 16) * 2);
                #pragma unroll
                for (int mt = 0; mt < 4; mt++) {
                    mma_f16(acc[mt][ntp * 2 + 0], af[mt], bf + 0);
                    mma_f16(acc[mt][ntp * 2 + 1], af[mt], bf + 2);
                }
            }
        }
    }
    __syncthreads();

    // epilogue: bias + act -> half, stage in smem, coalesced store
    __half* stage = tiles;      // 128 x 136 halfs = 34816 B < DYNSM
    #pragma unroll
    for (int mt = 0; mt < 4; mt++) {
        #pragma unroll
        for (int nt = 0; nt < 4; nt++) {
            int col = wn + nt * 8 + 2 * tig;
            float bx = bias[n0 + col], by = bias[n0 + col + 1];
            float v0 = acc[mt][nt][0] + bx, v1 = acc[mt][nt][1] + by;
            float v2 = acc[mt][nt][2] + bx, v3 = acc[mt][nt][3] + by;
            if (RELU) {
                v0 = fmaxf(v0, 0.f); v1 = fmaxf(v1, 0.f);
                v2 = fmaxf(v2, 0.f); v3 = fmaxf(v3, 0.f);
            }
            int r0 = wm + mt * 16 + gid;
            *(__half2*)&stage[r0 * 136 + col]       = __floats2half2_rn(v0, v1);
            *(__half2*)&stage[(r0 + 8) * 136 + col] = __floats2half2_rn(v2, v3);
        }
    }
    __syncthreads();
    #pragma unroll
    for (int i = 0; i < 8; i++) {
        int idx = tid + 256 * i;            // 0..2047
        int r = idx >> 4, c8 = (idx & 15) * 8;
        if (z == 0 || m0 + r < cnt) {
            uint4 v = *(uint4*)&stage[r * 136 + c8];
            *(uint4*)&C[(size_t)rowC[r] * N + n0 + c8] = v;
        }
    }
}

// ---------------- K_final: STAR fusion + final MLP + sigmoid ----------------
__global__ void k_final(const float* __restrict__ fW1, const float* __restrict__ fb1,
                        const float* __restrict__ fW2, const float* __restrict__ fb2,
                        float* __restrict__ out)
{
    int r = blockIdx.x;
    int t = threadIdx.x;
    __shared__ float fs[128];
    __shared__ float red[64];
    fs[t] = __half2float(g_hc[r * 128 + t]) * tanhf(__half2float(g_hd[r * 128 + t]));
    __syncthreads();
    if (t < 64) {
        float s = fb1[t];
        #pragma unroll
        for (int j = 0; j < 128; j++) s = fmaf(fs[j], fW1[j * 64 + t], s);
        red[t] = fmaxf(s, 0.f) * fW2[t];
    }
    __syncthreads();
    if (t < 32) {
        float v = red[t] + red[t + 32];
        #pragma unroll
        for (int o = 16; o; o >>= 1) v += __shfl_down_sync(0xffffffffu, v, o);
        if (t == 0) {
            float logit = v + fb2[0] + g_aux[r];
            out[r] = 1.f / (1.f + expf(-logit));
        }
    }
}

// ---------------- launch -----------------------------------------------------
extern "C" void kernel_launch(void* const* d_in, const int* in_sizes, int n_in,
                              void* d_out, int out_size)
{
    const float* x    = (const float*)d_in[0];
    const int*   dom  = (const int*)  d_in[1];
    const float* pnw  = (const float*)d_in[2];
    const float* pnb  = (const float*)d_in[3];
    const float* demb = (const float*)d_in[4];
    const float* cw   = (const float*)d_in[5];
    const float* cb   = (const float*)d_in[6];
    const float* cW1  = (const float*)d_in[7];
    const float* cb1  = (const float*)d_in[8];
    const float* cW2  = (const float*)d_in[9];
    const float* cb2  = (const float*)d_in[10];
    const float* cW3  = (const float*)d_in[11];
    const float* cb3  = (const float*)d_in[12];
    const float* dW1  = (const float*)d_in[13];
    const float* db1  = (const float*)d_in[14];
    const float* dW2  = (const float*)d_in[15];
    const float* db2  = (const float*)d_in[16];
    const float* dW3  = (const float*)d_in[17];
    const float* db3  = (const float*)d_in[18];
    const float* fW1  = (const float*)d_in[19];
    const float* fb1  = (const float*)d_in[20];
    const float* fW2  = (const float*)d_in[21];
    const float* fb2  = (const float*)d_in[22];
    const float* aW1  = (const float*)d_in[23];
    const float* ab1  = (const float*)d_in[24];
    const float* aW2  = (const float*)d_in[25];
    const float* ab2  = (const float*)d_in[26];
    float* out = (float*)d_out;

    __half *xcP, *ch1P, *ch2P, *hcP, *dg1P, *dg2P, *hdP;
    __half *wh1cP, *wh1dP, *wh2cP, *wh2dP, *wh3cP, *wh3dP;
    cudaGetSymbolAddress((void**)&xcP,  g_xc);
    cudaGetSymbolAddress((void**)&ch1P, g_ch1);
    cudaGetSymbolAddress((void**)&ch2P, g_ch2);
    cudaGetSymbolAddress((void**)&hcP,  g_hc);
    cudaGetSymbolAddress((void**)&dg1P, g_dg1);
    cudaGetSymbolAddress((void**)&dg2P, g_dg2);
    cudaGetSymbolAddress((void**)&hdP,  g_hd);
    cudaGetSymbolAddress((void**)&wh1cP, g_wh1c);
    cudaGetSymbolAddress((void**)&wh1dP, g_wh1d);
    cudaGetSymbolAddress((void**)&wh2cP, g_wh2c);
    cudaGetSymbolAddress((void**)&wh2dP, g_wh2d);
    cudaGetSymbolAddress((void**)&wh3cP, g_wh3c);
    cudaGetSymbolAddress((void**)&wh3dP, g_wh3d);

    cudaFuncSetAttribute(gemm_f16<K1P, 512, true,  1>, cudaFuncAttributeMaxDynamicSharedMemorySize, DYNSM);
    cudaFuncSetAttribute(gemm_f16<512, 256, true,  2>, cudaFuncAttributeMaxDynamicSharedMemorySize, DYNSM);
    cudaFuncSetAttribute(gemm_f16<256, 128, false, 3>, cudaFuncAttributeMaxDynamicSharedMemorySize, DYNSM);

    k_cvt<<<CVT_BLOCKS, 256>>>(cW1, dW1, cW2, dW2, cW3, dW3);
    k_part<<<1, 1024>>>(dom);
    k_prep<<<Bsz, 256>>>(x, dom, pnw, pnb, demb, cw, cb, aW1, ab1, aW2, ab2);

    // layer 1: K=1088(padded) -> N=512 ; z=0 center, z=1..8 domains
    gemm_f16<K1P, 512, true,  1><<<dim3(4, 32, 9), 256, DYNSM>>>(xcP,  xcP,  wh1cP, wh1dP, cb1, db1, ch1P, dg1P);
    // layer 2: K=512 -> N=256
    gemm_f16<512, 256, true,  2><<<dim3(2, 32, 9), 256, DYNSM>>>(ch1P, dg1P, wh2cP, wh2dP, cb2, db2, ch2P, dg2P);
    // layer 3: K=256 -> N=128
    gemm_f16<256, 128, false, 3><<<dim3(1, 32, 9), 256, DYNSM>>>(ch2P, dg2P, wh3cP, wh3dP, cb3, db3, hcP, hdP);

    k_final<<<Bsz, 128>>>(fW1, fb1, fW2, fb2, out);
}